// round 13
// baseline (speedup 1.0000x reference)
#include <cuda_runtime.h>
#include <cuda_fp16.h>
#include <math.h>
#include <stdint.h>

#define B_  2
#define S_  2048
#define D_  1024
#define H_  16
#define DK_ 64
#define M_  (B_*S_)   // 4096

// ---------------- scratch ------------------------------------------------------
// activations into GEMMs: hi+lo planes; weights, K-proj, V^T: hi-only
__device__ __half g_qih[(size_t)M_*D_]; __device__ __half g_qil[(size_t)M_*D_];
__device__ __half g_kih[(size_t)M_*D_]; __device__ __half g_kil[(size_t)M_*D_];
__device__ __half g_vih[(size_t)M_*D_]; __device__ __half g_vil[(size_t)M_*D_];
__device__ __half g_wqh[(size_t)D_*D_];
__device__ __half g_wkh[(size_t)D_*D_];
__device__ __half g_wvh[(size_t)D_*D_];
__device__ __half g_woh[(size_t)D_*D_];
__device__ __half g_qph[(size_t)B_*H_*S_*DK_]; __device__ __half g_qpl[(size_t)B_*H_*S_*DK_];
__device__ __half g_kph[(size_t)B_*H_*S_*DK_];
__device__ __half g_vth[(size_t)B_*H_*DK_*S_];
__device__ __half g_aph[(size_t)M_*D_]; __device__ __half g_apl[(size_t)M_*D_];

// ---------------- helpers -----------------------------------------------------
__device__ __forceinline__ uint32_t smem_to_u32(const void* p) {
    uint32_t a;
    asm("{ .reg .u64 t; cvta.to.shared.u64 t, %1; cvt.u32.u64 %0, t; }"
        : "=r"(a) : "l"(p));
    return a;
}
__device__ __forceinline__ void cp_async16(uint32_t dst, const void* src) {
    asm volatile("cp.async.ca.shared.global [%0], [%1], 16;" :: "r"(dst), "l"(src));
}
#define CP_COMMIT() asm volatile("cp.async.commit_group;" ::: "memory")
#define CP_WAIT(n)  asm volatile("cp.async.wait_group %0;" :: "n"(n) : "memory")

#define LDSM4(r0,r1,r2,r3,addr) \
    asm volatile("ldmatrix.sync.aligned.m8n8.x4.shared.b16 {%0,%1,%2,%3}, [%4];" \
        : "=r"(r0),"=r"(r1),"=r"(r2),"=r"(r3) : "r"(addr))

__device__ __forceinline__ void split2(float x, float y, uint32_t& h2, uint32_t& l2) {
    __half2 hp = __floats2half2_rn(x, y);
    const float lx = x - __half2float(__low2half(hp));
    const float ly = y - __half2float(__high2half(hp));
    __half2 lp = __floats2half2_rn(lx, ly);
    h2 = *reinterpret_cast<uint32_t*>(&hp);
    l2 = *reinterpret_cast<uint32_t*>(&lp);
}

// NOT volatile: pure register op; lets ptxas schedule across MMAs.
__device__ __forceinline__ void mma_f16(float* d, const uint32_t* a, const uint32_t* b) {
    asm("mma.sync.aligned.m16n8k16.row.col.f32.f16.f16.f32 "
        "{%0,%1,%2,%3}, {%4,%5,%6,%7}, {%8,%9}, {%0,%1,%2,%3};"
        : "+f"(d[0]), "+f"(d[1]), "+f"(d[2]), "+f"(d[3])
        : "r"(a[0]), "r"(a[1]), "r"(a[2]), "r"(a[3]), "r"(b[0]), "r"(b[1]));
}

// ---------------- prep: inputs hi+lo, weights hi-only, one launch -------------
__global__ __launch_bounds__(256) void split_all(
    const float4* __restrict__ q,  const float4* __restrict__ k,
    const float4* __restrict__ v,  const float4* __restrict__ wq,
    const float4* __restrict__ wk, const float4* __restrict__ wv,
    const float4* __restrict__ wo)
{
    const int t = blockIdx.y;
    const size_t i = (size_t)blockIdx.x * 256 + threadIdx.x;   // per float4
    const size_t n = (t < 3) ? (size_t)M_*D_/4 : (size_t)D_*D_/4;
    if (i >= n) return;
    const float4* src; __half *dh, *dl = nullptr;
    switch (t) {
        case 0:  src = q;  dh = g_qih; dl = g_qil; break;
        case 1:  src = k;  dh = g_kih; dl = g_kil; break;
        case 2:  src = v;  dh = g_vih; dl = g_vil; break;
        case 3:  src = wq; dh = g_wqh; break;
        case 4:  src = wk; dh = g_wkh; break;
        case 5:  src = wv; dh = g_wvh; break;
        default: src = wo; dh = g_woh; break;
    }
    const float4 x = src[i];
    uint32_t h0, l0, h1, l1;
    split2(x.x, x.y, h0, l0);
    split2(x.z, x.w, h1, l1);
    ((uint2*)dh)[i] = make_uint2(h0, h1);
    if (dl) ((uint2*)dl)[i] = make_uint2(l0, l1);
}

// ---------------- 2-term GEMM mainloop, warp phase-staggered ------------------
#define AST 40                          // halves per smem row (32 + 8 pad)
#define PLANE (128*AST)                 // halves per stage-plane
#define GEMM_SMEM 69632                 // max(3 planes x 2 stages = 61440, V-tile 67584)

__device__ __forceinline__ void gemm_mainloop(
    const __half* __restrict__ Agh, const __half* __restrict__ Agl,
    const __half* __restrict__ Wgh,
    uint32_t sAh, uint32_t sAl, uint32_t sBh,
    int m0, int n0, int tid, int wm, int wn, int lane,
    float acc[2][8][4])
{
    const int wid = tid >> 5;
    const int kfirst = (wid >> 2) & 1;             // warps 0-3 phase 0, 4-7 phase 1
    const int lr = lane & 7;
    const int a_ro = lr + ((lane >> 3) & 1) * 8;   // A ldmatrix row offset
    const int a_co = ((lane >> 4) & 1) * 8;        // A col offset
    const int b_ro = lr + ((lane >> 4) & 1) * 8;   // B row offset
    const int b_co = ((lane >> 3) & 1) * 8;        // B col offset

    #define G_LOAD(st, chk) do { \
        _Pragma("unroll") \
        for (int i = 0; i < 2; i++) { \
            const int idx = tid + i*256, row = idx >> 2, seg = idx & 3; \
            const uint32_t so = (uint32_t)((((st)*128+row)*AST + seg*8)*2); \
            cp_async16(sAh + so, Agh + (size_t)(m0+row)*1024 + (chk)*32 + seg*8); \
            cp_async16(sAl + so, Agl + (size_t)(m0+row)*1024 + (chk)*32 + seg*8); \
            cp_async16(sBh + so, Wgh + (size_t)(n0+row)*1024 + (chk)*32 + seg*8); \
        } \
    } while (0)

    G_LOAD(0, 0); CP_COMMIT();

    for (int chk = 0; chk < 32; chk++) {
        const int st = chk & 1;
        if (chk < 31) { G_LOAD(st^1, chk+1); CP_COMMIT(); CP_WAIT(1); }
        else CP_WAIT(0);
        __syncthreads();

        const uint32_t stoff = (uint32_t)(st*PLANE*2);
        #pragma unroll
        for (int ksi = 0; ksi < 2; ksi++) {
            const int ks = ksi ^ kfirst;           // phase-staggered k-slice
            uint32_t ah[2][4], al[2][4];
            #pragma unroll
            for (int mt = 0; mt < 2; mt++) {
                const uint32_t ao = stoff +
                    (uint32_t)(((wm + mt*16 + a_ro)*AST + ks*16 + a_co)*2);
                LDSM4(ah[mt][0], ah[mt][1], ah[mt][2], ah[mt][3], sAh + ao);
                LDSM4(al[mt][0], al[mt][1], al[mt][2], al[mt][3], sAl + ao);
            }
            #pragma unroll
            for (int np = 0; np < 4; np++) {
                const uint32_t bo = stoff +
                    (uint32_t)(((wn + np*16 + b_ro)*AST + ks*16 + b_co)*2);
                uint32_t b0h, b1h, b2h, b3h;
                LDSM4(b0h, b1h, b2h, b3h, sBh + bo);
                uint32_t bhA[2] = {b0h, b1h}, bhB[2] = {b2h, b3h};
                #pragma unroll
                for (int mt = 0; mt < 2; mt++) {
                    mma_f16(acc[mt][2*np  ], ah[mt], bhA);
                    mma_f16(acc[mt][2*np+1], ah[mt], bhB);
                }
                #pragma unroll
                for (int mt = 0; mt < 2; mt++) {
                    mma_f16(acc[mt][2*np  ], al[mt], bhA);
                    mma_f16(acc[mt][2*np+1], al[mt], bhB);
                }
            }
        }
        __syncthreads();
    }
    #undef G_LOAD
}

// ---------------- merged Q/K/V projection GEMM --------------------------------
// z=0: Q -> hi+lo planes. z=1: K -> hi-only. z=2: V -> transposed hi-only.
__global__ __launch_bounds__(256, 2) void gemm_qkv(
    const float* __restrict__ bq, const float* __restrict__ bk,
    const float* __restrict__ bv)
{
    extern __shared__ __half smh[];
    const uint32_t base = smem_to_u32(smh);
    const uint32_t sAh = base, sAl = base + 2*PLANE*2, sBh = base + 4*PLANE*2;
    const int tid = threadIdx.x, lane = tid & 31, wid = tid >> 5;
    const int g = lane >> 2, c = lane & 3;
    const int wm = (wid & 3)*32, wn = (wid >> 2)*64;
    const int m0 = blockIdx.x*128, n0 = blockIdx.y*128;
    const int z = blockIdx.z;

    const __half *Agh, *Agl, *Wgh;
    const float* bias;
    if (z == 0) { Agh=g_qih; Agl=g_qil; Wgh=g_wqh; bias=bq; }
    else if (z == 1) { Agh=g_kih; Agl=g_kil; Wgh=g_wkh; bias=bk; }
    else { Agh=g_vih; Agl=g_vil; Wgh=g_wvh; bias=bv; }

    float acc[2][8][4] = {};
    gemm_mainloop(Agh, Agl, Wgh, sAh, sAl, sBh, m0, n0, tid, wm, wn, lane, acc);

    if (z == 0) {
        #pragma unroll
        for (int mt = 0; mt < 2; mt++)
          #pragma unroll
          for (int hf = 0; hf < 2; hf++) {
            const int m = m0 + wm + mt*16 + g + hf*8;
            const int bb = m >> 11, ss = m & (S_-1);
            #pragma unroll
            for (int nt = 0; nt < 8; nt++) {
                const int n = n0 + wn + nt*8 + c*2;
                const int hh = n >> 6, dk = n & 63;
                uint32_t h2, l2;
                split2(acc[mt][nt][hf*2+0] + bias[n],
                       acc[mt][nt][hf*2+1] + bias[n+1], h2, l2);
                const size_t o = ((((size_t)bb*H_ + hh)*S_ + ss)*DK_ + dk) >> 1;
                ((uint32_t*)g_qph)[o] = h2;
                ((uint32_t*)g_qpl)[o] = l2;
            }
          }
    } else if (z == 1) {
        #pragma unroll
        for (int mt = 0; mt < 2; mt++)
          #pragma unroll
          for (int hf = 0; hf < 2; hf++) {
            const int m = m0 + wm + mt*16 + g + hf*8;
            const int bb = m >> 11, ss = m & (S_-1);
            #pragma unroll
            for (int nt = 0; nt < 8; nt++) {
                const int n = n0 + wn + nt*8 + c*2;
                const int hh = n >> 6, dk = n & 63;
                const __half2 hp = __floats2half2_rn(acc[mt][nt][hf*2+0] + bias[n],
                                                     acc[mt][nt][hf*2+1] + bias[n+1]);
                const size_t o = ((((size_t)bb*H_ + hh)*S_ + ss)*DK_ + dk) >> 1;
                ((__half2*)g_kph)[o] = hp;
            }
          }
    } else {
        // V: transpose through smem (reuse staging buffers), write V^T hi plane
        float* tile = (float*)smh;   // [128 n][132]
        __syncthreads();
        #pragma unroll
        for (int mt = 0; mt < 2; mt++)
          #pragma unroll
          for (int hf = 0; hf < 2; hf++) {
            const int ml = wm + mt*16 + g + hf*8;
            #pragma unroll
            for (int nt = 0; nt < 8; nt++) {
                const int nl = wn + nt*8 + c*2;
                tile[(nl  )*132 + ml] = acc[mt][nt][hf*2+0] + bias[n0+nl];
                tile[(nl+1)*132 + ml] = acc[mt][nt][hf*2+1] + bias[n0+nl+1];
            }
          }
        __syncthreads();
        const int bb = m0 >> 11, s0 = m0 & (S_-1);
        #pragma unroll
        for (int i = 0; i < 32; i++) {
            const int idx = tid + i*256;      // 0..8191
            const int nl = idx >> 6;          // 0..127
            const int sp = idx & 63;          // 0..63 (s-pair)
            const int hh = (n0 + nl) >> 6, dk = (n0 + nl) & 63;
            const __half2 hp = __floats2half2_rn(tile[nl*132 + 2*sp],
                                                 tile[nl*132 + 2*sp + 1]);
            const size_t o = ((((size_t)bb*H_ + hh)*DK_ + dk)*S_ + s0 + 2*sp) >> 1;
            ((__half2*)g_vth)[o] = hp;
        }
    }
}

// ---------------- output GEMM -------------------------------------------------
__global__ __launch_bounds__(256, 2) void gemm_out(const float* __restrict__ bias,
                                                   float* __restrict__ C)
{
    extern __shared__ __half smh[];
    const uint32_t base = smem_to_u32(smh);
    const uint32_t sAh = base, sAl = base + 2*PLANE*2, sBh = base + 4*PLANE*2;
    const int tid = threadIdx.x, lane = tid & 31, wid = tid >> 5;
    const int g = lane >> 2, c = lane & 3;
    const int wm = (wid & 3)*32, wn = (wid >> 2)*64;
    const int m0 = blockIdx.x*128, n0 = blockIdx.y*128;

    float acc[2][8][4] = {};
    gemm_mainloop(g_aph, g_apl, g_woh, sAh, sAl, sBh, m0, n0, tid, wm, wn, lane, acc);

    #pragma unroll
    for (int mt = 0; mt < 2; mt++)
      #pragma unroll
      for (int hf = 0; hf < 2; hf++) {
        const int m = m0 + wm + mt*16 + g + hf*8;
        #pragma unroll
        for (int nt = 0; nt < 8; nt++) {
            const int n = n0 + wn + nt*8 + c*2;
            *(float2*)(C + (size_t)m*D_ + n) =
                make_float2(acc[mt][nt][hf*2+0] + bias[n],
                            acc[mt][nt][hf*2+1] + bias[n+1]);
        }
      }
}

// ---------------- fp16 flash attention (QK 2-term, PV 1-plane, staggered) -----
#define TST 72                          // halves per smem row (64 + 8 pad)
#define SM_QH 0
#define SM_QL (128*TST)
#define SM_KH (2*128*TST)
#define SM_VH (SM_KH + 2*64*TST)
#define ATTN_SMEM ((SM_VH + 2*64*TST)*2)   // 73728 B

__global__ __launch_bounds__(256, 2) void attn_f16()
{
    extern __shared__ __half smh[];
    const uint32_t base = smem_to_u32(smh);
    const int tid = threadIdx.x, lane = tid & 31, wid = tid >> 5;
    const int g = lane >> 2, c = lane & 3;
    const int wr = wid * 16;
    const int wph = wid & 3;               // per-warp phase for k-slice stagger
    const int h = blockIdx.y, b = blockIdx.z;
    const int q0 = blockIdx.x * 128;
    const size_t bh = (size_t)b*H_ + h;
    const __half* qgh = g_qph + (bh*S_ + q0)*DK_;
    const __half* qgl = g_qpl + (bh*S_ + q0)*DK_;
    const __half* kgh = g_kph + bh*S_*DK_;
    const __half* vgh = g_vth + bh*DK_*S_;

    const int lr = lane & 7;
    const int a_ro = lr + ((lane >> 3) & 1) * 8;
    const int a_co = ((lane >> 4) & 1) * 8;
    const int b_ro = lr + ((lane >> 4) & 1) * 8;
    const int b_co = ((lane >> 3) & 1) * 8;

    // prologue: Q planes + K/V tile 0
    #pragma unroll
    for (int i = 0; i < 4; i++) {
        const int idx = tid + i*256;          // 0..1023
        const int row = idx >> 3, seg = idx & 7;
        const uint32_t so = (uint32_t)((row*TST + seg*8)*2);
        cp_async16(base + SM_QH*2 + so, qgh + (size_t)row*DK_ + seg*8);
        cp_async16(base + SM_QL*2 + so, qgl + (size_t)row*DK_ + seg*8);
    }
    #pragma unroll
    for (int i = 0; i < 2; i++) {
        const int idx = tid + i*256;          // 0..511
        const int row = idx >> 3, seg = idx & 7;
        const uint32_t so = (uint32_t)((row*TST + seg*8)*2);
        cp_async16(base + SM_KH*2 + so, kgh + (size_t)row*DK_ + seg*8);
        cp_async16(base + SM_VH*2 + so, vgh + (size_t)row*S_ + seg*8);
    }
    CP_COMMIT();

    float o[8][4] = {};
    float mrun[2] = {-1e30f, -1e30f};
    float lrun[2] = {0.f, 0.f};

    for (int t = 0; t < S_/64; t++) {
        const int st = t & 1;
        if (t < S_/64 - 1) {
            const int s2 = st ^ 1;
            #pragma unroll
            for (int i = 0; i < 2; i++) {
                const int idx = tid + i*256;
                const int row = idx >> 3, seg = idx & 7;
                const uint32_t so = (uint32_t)(((s2*64 + row)*TST + seg*8)*2);
                cp_async16(base + SM_KH*2 + so, kgh + (size_t)((t+1)*64+row)*DK_ + seg*8);
                cp_async16(base + SM_VH*2 + so, vgh + (size_t)row*S_ + (t+1)*64 + seg*8);
            }
            CP_COMMIT(); CP_WAIT(1);
        } else {
            CP_WAIT(0);
        }
        __syncthreads();

        const uint32_t kst  = (uint32_t)((SM_KH + st*64*TST)*2);
        const uint32_t vhst = (uint32_t)((SM_VH + st*64*TST)*2);

        // ---- S = (Q K^T)/8  = (Qh+Ql)·Kh (2-term, phase-staggered) ----------
        float s[8][4] = {};
        #pragma unroll
        for (int ksi = 0; ksi < 4; ksi++) {
            const int ks = (ksi + wph) & 3;
            const uint32_t qo = (uint32_t)(((wr + a_ro)*TST + ks*16 + a_co)*2);
            uint32_t ah[4], al[4];
            LDSM4(ah[0], ah[1], ah[2], ah[3], base + SM_QH*2 + qo);
            LDSM4(al[0], al[1], al[2], al[3], base + SM_QL*2 + qo);
            #pragma unroll
            for (int np = 0; np < 4; np++) {
                const uint32_t ko = (uint32_t)(((np*16 + b_ro)*TST + ks*16 + b_co)*2);
                uint32_t b0h, b1h, b2h, b3h;
                LDSM4(b0h, b1h, b2h, b3h, base + kst + ko);
                uint32_t bhA[2] = {b0h, b1h}, bhB[2] = {b2h, b3h};
                mma_f16(s[2*np  ], ah, bhA);
                mma_f16(s[2*np+1], ah, bhB);
                mma_f16(s[2*np  ], al, bhA);
                mma_f16(s[2*np+1], al, bhB);
            }
        }

        // ---- online softmax (rows g, g+8; stats across 4 c-lanes) -----------
        #pragma unroll
        for (int hf = 0; hf < 2; hf++) {
            float mx = -1e30f;
            #pragma unroll
            for (int nt = 0; nt < 8; nt++) {
                s[nt][hf*2]   *= 0.125f;
                s[nt][hf*2+1] *= 0.125f;
                mx = fmaxf(mx, fmaxf(s[nt][hf*2], s[nt][hf*2+1]));
            }
            mx = fmaxf(mx, __shfl_xor_sync(0xffffffffu, mx, 1));
            mx = fmaxf(mx, __shfl_xor_sync(0xffffffffu, mx, 2));
            const float mn = fmaxf(mrun[hf], mx);
            const float corr = __expf(mrun[hf] - mn);
            mrun[hf] = mn;
            float ls = 0.f;
            #pragma unroll
            for (int nt = 0; nt < 8; nt++) {
                const float e0 = __expf(s[nt][hf*2]   - mn);
                const float e1 = __expf(s[nt][hf*2+1] - mn);
                s[nt][hf*2] = e0; s[nt][hf*2+1] = e1;
                ls += e0 + e1;
            }
            ls += __shfl_xor_sync(0xffffffffu, ls, 1);
            ls += __shfl_xor_sync(0xffffffffu, ls, 2);
            lrun[hf] = lrun[hf]*corr + ls;
            #pragma unroll
            for (int nt = 0; nt < 8; nt++) {
                o[nt][hf*2]   *= corr;
                o[nt][hf*2+1] *= corr;
            }
        }

        // ---- P fragments directly from acc registers ------------------------
        uint32_t pa[4][4];
        #pragma unroll
        for (int kv = 0; kv < 4; kv++) {
            __half2 h0 = __floats2half2_rn(s[2*kv  ][0], s[2*kv  ][1]);
            __half2 h1 = __floats2half2_rn(s[2*kv  ][2], s[2*kv  ][3]);
            __half2 h2 = __floats2half2_rn(s[2*kv+1][0], s[2*kv+1][1]);
            __half2 h3 = __floats2half2_rn(s[2*kv+1][2], s[2*kv+1][3]);
            pa[kv][0] = *reinterpret_cast<uint32_t*>(&h0);
            pa[kv][1] = *reinterpret_cast<uint32_t*>(&h1);
            pa[kv][2] = *reinterpret_cast<uint32_t*>(&h2);
            pa[kv][3] = *reinterpret_cast<uint32_t*>(&h3);
        }

        // ---- O += P Vh (1-plane V, phase-staggered) --------------------------
        #pragma unroll
        for (int kvi = 0; kvi < 4; kvi++) {
            const int kv = (kvi + wph) & 3;
            #pragma unroll
            for (int np = 0; np < 4; np++) {
                const uint32_t vo = (uint32_t)(((np*16 + b_ro)*TST + kv*16 + b_co)*2);
                uint32_t v0h, v1h, v2h, v3h;
                LDSM4(v0h, v1h, v2h, v3h, base + vhst + vo);
                uint32_t vhA[2] = {v0h, v1h}, vhB[2] = {v2h, v3h};
                mma_f16(o[2*np  ], pa[kv], vhA);
                mma_f16(o[2*np+1], pa[kv], vhB);
            }
        }
        __syncthreads();
    }

    // epilogue: normalize, split, store hi/lo planes for the O-GEMM
    #pragma unroll
    for (int hf = 0; hf < 2; hf++) {
        const int r = q0 + wr + g + hf*8;
        const float inv = 1.f / lrun[hf];
        #pragma unroll
        for (int nt = 0; nt < 8; nt++) {
            const int col = h*DK_ + nt*8 + c*2;
            uint32_t h2, l2;
            split2(o[nt][hf*2]*inv, o[nt][hf*2+1]*inv, h2, l2);
            const size_t off = (((size_t)b*S_ + r)*D_ + col) >> 1;
            ((uint32_t*)g_aph)[off] = h2;
            ((uint32_t*)g_apl)[off] = l2;
        }
    }
}

// ---------------- launch ------------------------------------------------------
extern "C" void kernel_launch(void* const* d_in, const int* in_sizes, int n_in,
                              void* d_out, int out_size)
{
    (void)in_sizes; (void)n_in; (void)out_size;
    const float* Q  = (const float*)d_in[0];
    const float* K  = (const float*)d_in[1];
    const float* V  = (const float*)d_in[2];
    const float* Wq = (const float*)d_in[3];
    const float* bq = (const float*)d_in[4];
    const float* Wk = (const float*)d_in[5];
    const float* bk = (const float*)d_in[6];
    const float* Wv = (const float*)d_in[7];
    const float* bv = (const float*)d_in[8];
    const float* Wo = (const float*)d_in[9];
    const float* bo = (const float*)d_in[10];
    float* out = (float*)d_out;

    cudaFuncSetAttribute(gemm_qkv, cudaFuncAttributeMaxDynamicSharedMemorySize, GEMM_SMEM);
    cudaFuncSetAttribute(gemm_out, cudaFuncAttributeMaxDynamicSharedMemorySize, GEMM_SMEM);
    cudaFuncSetAttribute(attn_f16, cudaFuncAttributeMaxDynamicSharedMemorySize, ATTN_SMEM);

    split_all<<<dim3(4096, 7), 256>>>((const float4*)Q,  (const float4*)K,
                                      (const float4*)V,  (const float4*)Wq,
                                      (const float4*)Wk, (const float4*)Wv,
                                      (const float4*)Wo);

    gemm_qkv<<<dim3(M_/128, D_/128, 3), 256, GEMM_SMEM>>>(bq, bk, bv);

    attn_f16<<<dim3(S_/128, H_, B_), 256, ATTN_SMEM>>>();

    gemm_out<<<dim3(M_/128, D_/128), 256, GEMM_SMEM>>>(bo, out);
}

// round 14
// speedup vs baseline: 1.0764x; 1.0764x over previous
#include <cuda_runtime.h>
#include <cuda_fp16.h>
#include <math.h>
#include <stdint.h>

#define B_  2
#define S_  2048
#define D_  1024
#define H_  16
#define DK_ 64
#define M_  (B_*S_)   // 4096

// ---------------- scratch ------------------------------------------------------
__device__ __half g_qih[(size_t)M_*D_]; __device__ __half g_qil[(size_t)M_*D_];
__device__ __half g_kih[(size_t)M_*D_]; __device__ __half g_kil[(size_t)M_*D_];
__device__ __half g_vih[(size_t)M_*D_]; __device__ __half g_vil[(size_t)M_*D_];
__device__ __half g_wqh[(size_t)D_*D_];
__device__ __half g_wkh[(size_t)D_*D_];
__device__ __half g_wvh[(size_t)D_*D_];
__device__ __half g_woh[(size_t)D_*D_];
__device__ __half g_qph[(size_t)B_*H_*S_*DK_]; __device__ __half g_qpl[(size_t)B_*H_*S_*DK_];
__device__ __half g_kph[(size_t)B_*H_*S_*DK_];
__device__ __half g_vth[(size_t)B_*H_*DK_*S_];
__device__ __half g_aph[(size_t)M_*D_]; __device__ __half g_apl[(size_t)M_*D_];

// ---------------- helpers -----------------------------------------------------
__device__ __forceinline__ uint32_t smem_to_u32(const void* p) {
    uint32_t a;
    asm("{ .reg .u64 t; cvta.to.shared.u64 t, %1; cvt.u32.u64 %0, t; }"
        : "=r"(a) : "l"(p));
    return a;
}
__device__ __forceinline__ void cp_async16(uint32_t dst, const void* src) {
    asm volatile("cp.async.ca.shared.global [%0], [%1], 16;" :: "r"(dst), "l"(src));
}
#define CP_COMMIT() asm volatile("cp.async.commit_group;" ::: "memory")
#define CP_WAIT(n)  asm volatile("cp.async.wait_group %0;" :: "n"(n) : "memory")

#define LDSM4(r0,r1,r2,r3,addr) \
    asm volatile("ldmatrix.sync.aligned.m8n8.x4.shared.b16 {%0,%1,%2,%3}, [%4];" \
        : "=r"(r0),"=r"(r1),"=r"(r2),"=r"(r3) : "r"(addr))

__device__ __forceinline__ void split2(float x, float y, uint32_t& h2, uint32_t& l2) {
    __half2 hp = __floats2half2_rn(x, y);
    const float lx = x - __half2float(__low2half(hp));
    const float ly = y - __half2float(__high2half(hp));
    __half2 lp = __floats2half2_rn(lx, ly);
    h2 = *reinterpret_cast<uint32_t*>(&hp);
    l2 = *reinterpret_cast<uint32_t*>(&lp);
}

__device__ __forceinline__ void mma_f16(float* d, const uint32_t* a, const uint32_t* b) {
    asm("mma.sync.aligned.m16n8k16.row.col.f32.f16.f16.f32 "
        "{%0,%1,%2,%3}, {%4,%5,%6,%7}, {%8,%9}, {%0,%1,%2,%3};"
        : "+f"(d[0]), "+f"(d[1]), "+f"(d[2]), "+f"(d[3])
        : "r"(a[0]), "r"(a[1]), "r"(a[2]), "r"(a[3]), "r"(b[0]), "r"(b[1]));
}

// ---------------- prep: inputs hi+lo, weights hi-only, one launch -------------
__global__ __launch_bounds__(256) void split_all(
    const float4* __restrict__ q,  const float4* __restrict__ k,
    const float4* __restrict__ v,  const float4* __restrict__ wq,
    const float4* __restrict__ wk, const float4* __restrict__ wv,
    const float4* __restrict__ wo)
{
    const int t = blockIdx.y;
    const size_t i = (size_t)blockIdx.x * 256 + threadIdx.x;   // per float4
    const size_t n = (t < 3) ? (size_t)M_*D_/4 : (size_t)D_*D_/4;
    if (i >= n) return;
    const float4* src; __half *dh, *dl = nullptr;
    switch (t) {
        case 0:  src = q;  dh = g_qih; dl = g_qil; break;
        case 1:  src = k;  dh = g_kih; dl = g_kil; break;
        case 2:  src = v;  dh = g_vih; dl = g_vil; break;
        case 3:  src = wq; dh = g_wqh; break;
        case 4:  src = wk; dh = g_wkh; break;
        case 5:  src = wv; dh = g_wvh; break;
        default: src = wo; dh = g_woh; break;
    }
    const float4 x = src[i];
    uint32_t h0, l0, h1, l1;
    split2(x.x, x.y, h0, l0);
    split2(x.z, x.w, h1, l1);
    ((uint2*)dh)[i] = make_uint2(h0, h1);
    if (dl) ((uint2*)dl)[i] = make_uint2(l0, l1);
}

// ---------------- 2-term GEMM mainloop: 4 warps, warp-tile 64x64 --------------
#define AST 40                          // halves per smem row (32 + 8 pad)
#define PLANE (128*AST)                 // halves per stage-plane
#define GEMM_SMEM 69632                 // max(3 planes x 2 stages = 61440, V-tile 67584)

__device__ __forceinline__ void gemm_mainloop(
    const __half* __restrict__ Agh, const __half* __restrict__ Agl,
    const __half* __restrict__ Wgh,
    uint32_t sAh, uint32_t sAl, uint32_t sBh,
    int m0, int n0, int tid, int wm, int wn, int lane,
    float acc[4][8][4])
{
    const int lr = lane & 7;
    const int a_ro = lr + ((lane >> 3) & 1) * 8;   // A ldmatrix row offset
    const int a_co = ((lane >> 4) & 1) * 8;        // A col offset
    const int b_ro = lr + ((lane >> 4) & 1) * 8;   // B row offset
    const int b_co = ((lane >> 3) & 1) * 8;        // B col offset

    #define G_LOAD(st, chk) do { \
        _Pragma("unroll") \
        for (int i = 0; i < 4; i++) { \
            const int idx = tid + i*128, row = idx >> 2, seg = idx & 3; \
            const uint32_t so = (uint32_t)((((st)*128+row)*AST + seg*8)*2); \
            cp_async16(sAh + so, Agh + (size_t)(m0+row)*1024 + (chk)*32 + seg*8); \
            cp_async16(sAl + so, Agl + (size_t)(m0+row)*1024 + (chk)*32 + seg*8); \
            cp_async16(sBh + so, Wgh + (size_t)(n0+row)*1024 + (chk)*32 + seg*8); \
        } \
    } while (0)

    G_LOAD(0, 0); CP_COMMIT();

    for (int chk = 0; chk < 32; chk++) {
        const int st = chk & 1;
        if (chk < 31) { G_LOAD(st^1, chk+1); CP_COMMIT(); CP_WAIT(1); }
        else CP_WAIT(0);
        __syncthreads();

        const uint32_t stoff = (uint32_t)(st*PLANE*2);
        #pragma unroll
        for (int ks = 0; ks < 2; ks++) {
            uint32_t ah[4][4], al[4][4];
            #pragma unroll
            for (int mt = 0; mt < 4; mt++) {
                const uint32_t ao = stoff +
                    (uint32_t)(((wm + mt*16 + a_ro)*AST + ks*16 + a_co)*2);
                LDSM4(ah[mt][0], ah[mt][1], ah[mt][2], ah[mt][3], sAh + ao);
                LDSM4(al[mt][0], al[mt][1], al[mt][2], al[mt][3], sAl + ao);
            }
            #pragma unroll
            for (int np = 0; np < 4; np++) {
                const uint32_t bo = stoff +
                    (uint32_t)(((wn + np*16 + b_ro)*AST + ks*16 + b_co)*2);
                uint32_t b0h, b1h, b2h, b3h;
                LDSM4(b0h, b1h, b2h, b3h, sBh + bo);
                uint32_t bhA[2] = {b0h, b1h}, bhB[2] = {b2h, b3h};
                #pragma unroll
                for (int mt = 0; mt < 4; mt++) {
                    mma_f16(acc[mt][2*np  ], ah[mt], bhA);
                    mma_f16(acc[mt][2*np+1], ah[mt], bhB);
                }
                #pragma unroll
                for (int mt = 0; mt < 4; mt++) {
                    mma_f16(acc[mt][2*np  ], al[mt], bhA);
                    mma_f16(acc[mt][2*np+1], al[mt], bhB);
                }
            }
        }
        __syncthreads();
    }
    #undef G_LOAD
}

// ---------------- merged Q/K/V projection GEMM (128 threads) ------------------
// z=0: Q -> hi+lo planes. z=1: K -> hi-only. z=2: V -> transposed hi-only.
__global__ __launch_bounds__(128, 2) void gemm_qkv(
    const float* __restrict__ bq, const float* __restrict__ bk,
    const float* __restrict__ bv)
{
    extern __shared__ __half smh[];
    const uint32_t base = smem_to_u32(smh);
    const uint32_t sAh = base, sAl = base + 2*PLANE*2, sBh = base + 4*PLANE*2;
    const int tid = threadIdx.x, lane = tid & 31, wid = tid >> 5;
    const int g = lane >> 2, c = lane & 3;
    const int wm = (wid & 1)*64, wn = (wid >> 1)*64;
    const int m0 = blockIdx.x*128, n0 = blockIdx.y*128;
    const int z = blockIdx.z;

    const __half *Agh, *Agl, *Wgh;
    const float* bias;
    if (z == 0) { Agh=g_qih; Agl=g_qil; Wgh=g_wqh; bias=bq; }
    else if (z == 1) { Agh=g_kih; Agl=g_kil; Wgh=g_wkh; bias=bk; }
    else { Agh=g_vih; Agl=g_vil; Wgh=g_wvh; bias=bv; }

    float acc[4][8][4] = {};
    gemm_mainloop(Agh, Agl, Wgh, sAh, sAl, sBh, m0, n0, tid, wm, wn, lane, acc);

    if (z == 0) {
        #pragma unroll
        for (int mt = 0; mt < 4; mt++)
          #pragma unroll
          for (int hf = 0; hf < 2; hf++) {
            const int m = m0 + wm + mt*16 + g + hf*8;
            const int bb = m >> 11, ss = m & (S_-1);
            #pragma unroll
            for (int nt = 0; nt < 8; nt++) {
                const int n = n0 + wn + nt*8 + c*2;
                const int hh = n >> 6, dk = n & 63;
                uint32_t h2, l2;
                split2(acc[mt][nt][hf*2+0] + bias[n],
                       acc[mt][nt][hf*2+1] + bias[n+1], h2, l2);
                const size_t o = ((((size_t)bb*H_ + hh)*S_ + ss)*DK_ + dk) >> 1;
                ((uint32_t*)g_qph)[o] = h2;
                ((uint32_t*)g_qpl)[o] = l2;
            }
          }
    } else if (z == 1) {
        #pragma unroll
        for (int mt = 0; mt < 4; mt++)
          #pragma unroll
          for (int hf = 0; hf < 2; hf++) {
            const int m = m0 + wm + mt*16 + g + hf*8;
            const int bb = m >> 11, ss = m & (S_-1);
            #pragma unroll
            for (int nt = 0; nt < 8; nt++) {
                const int n = n0 + wn + nt*8 + c*2;
                const int hh = n >> 6, dk = n & 63;
                const __half2 hp = __floats2half2_rn(acc[mt][nt][hf*2+0] + bias[n],
                                                     acc[mt][nt][hf*2+1] + bias[n+1]);
                const size_t o = ((((size_t)bb*H_ + hh)*S_ + ss)*DK_ + dk) >> 1;
                ((__half2*)g_kph)[o] = hp;
            }
          }
    } else {
        // V: transpose through smem (reuse staging buffers), write V^T hi plane
        float* tile = (float*)smh;   // [128 n][132]
        __syncthreads();
        #pragma unroll
        for (int mt = 0; mt < 4; mt++)
          #pragma unroll
          for (int hf = 0; hf < 2; hf++) {
            const int ml = wm + mt*16 + g + hf*8;
            #pragma unroll
            for (int nt = 0; nt < 8; nt++) {
                const int nl = wn + nt*8 + c*2;
                tile[(nl  )*132 + ml] = acc[mt][nt][hf*2+0] + bias[n0+nl];
                tile[(nl+1)*132 + ml] = acc[mt][nt][hf*2+1] + bias[n0+nl+1];
            }
          }
        __syncthreads();
        const int bb = m0 >> 11, s0 = m0 & (S_-1);
        #pragma unroll
        for (int i = 0; i < 64; i++) {
            const int idx = tid + i*128;      // 0..8191
            const int nl = idx >> 6;          // 0..127
            const int sp = idx & 63;          // 0..63 (s-pair)
            const int hh = (n0 + nl) >> 6, dk = (n0 + nl) & 63;
            const __half2 hp = __floats2half2_rn(tile[nl*132 + 2*sp],
                                                 tile[nl*132 + 2*sp + 1]);
            const size_t o = ((((size_t)bb*H_ + hh)*DK_ + dk)*S_ + s0 + 2*sp) >> 1;
            ((__half2*)g_vth)[o] = hp;
        }
    }
}

// ---------------- output GEMM (128 threads) -----------------------------------
__global__ __launch_bounds__(128, 2) void gemm_out(const float* __restrict__ bias,
                                                   float* __restrict__ C)
{
    extern __shared__ __half smh[];
    const uint32_t base = smem_to_u32(smh);
    const uint32_t sAh = base, sAl = base + 2*PLANE*2, sBh = base + 4*PLANE*2;
    const int tid = threadIdx.x, lane = tid & 31, wid = tid >> 5;
    const int g = lane >> 2, c = lane & 3;
    const int wm = (wid & 1)*64, wn = (wid >> 1)*64;
    const int m0 = blockIdx.x*128, n0 = blockIdx.y*128;

    float acc[4][8][4] = {};
    gemm_mainloop(g_aph, g_apl, g_woh, sAh, sAl, sBh, m0, n0, tid, wm, wn, lane, acc);

    #pragma unroll
    for (int mt = 0; mt < 4; mt++)
      #pragma unroll
      for (int hf = 0; hf < 2; hf++) {
        const int m = m0 + wm + mt*16 + g + hf*8;
        #pragma unroll
        for (int nt = 0; nt < 8; nt++) {
            const int n = n0 + wn + nt*8 + c*2;
            *(float2*)(C + (size_t)m*D_ + n) =
                make_float2(acc[mt][nt][hf*2+0] + bias[n],
                            acc[mt][nt][hf*2+1] + bias[n+1]);
        }
      }
}

// ---------------- fp16 flash attention (round-12 exact, no stagger) -----------
#define TST 72                          // halves per smem row (64 + 8 pad)
#define SM_QH 0
#define SM_QL (128*TST)
#define SM_KH (2*128*TST)
#define SM_VH (SM_KH + 2*64*TST)
#define ATTN_SMEM ((SM_VH + 2*64*TST)*2)   // 73728 B

__global__ __launch_bounds__(256, 2) void attn_f16()
{
    extern __shared__ __half smh[];
    const uint32_t base = smem_to_u32(smh);
    const int tid = threadIdx.x, lane = tid & 31, wid = tid >> 5;
    const int g = lane >> 2, c = lane & 3;
    const int wr = wid * 16;
    const int h = blockIdx.y, b = blockIdx.z;
    const int q0 = blockIdx.x * 128;
    const size_t bh = (size_t)b*H_ + h;
    const __half* qgh = g_qph + (bh*S_ + q0)*DK_;
    const __half* qgl = g_qpl + (bh*S_ + q0)*DK_;
    const __half* kgh = g_kph + bh*S_*DK_;
    const __half* vgh = g_vth + bh*DK_*S_;

    const int lr = lane & 7;
    const int a_ro = lr + ((lane >> 3) & 1) * 8;
    const int a_co = ((lane >> 4) & 1) * 8;
    const int b_ro = lr + ((lane >> 4) & 1) * 8;
    const int b_co = ((lane >> 3) & 1) * 8;

    // prologue: Q planes + K/V tile 0
    #pragma unroll
    for (int i = 0; i < 4; i++) {
        const int idx = tid + i*256;          // 0..1023
        const int row = idx >> 3, seg = idx & 7;
        const uint32_t so = (uint32_t)((row*TST + seg*8)*2);
        cp_async16(base + SM_QH*2 + so, qgh + (size_t)row*DK_ + seg*8);
        cp_async16(base + SM_QL*2 + so, qgl + (size_t)row*DK_ + seg*8);
    }
    #pragma unroll
    for (int i = 0; i < 2; i++) {
        const int idx = tid + i*256;          // 0..511
        const int row = idx >> 3, seg = idx & 7;
        const uint32_t so = (uint32_t)((row*TST + seg*8)*2);
        cp_async16(base + SM_KH*2 + so, kgh + (size_t)row*DK_ + seg*8);
        cp_async16(base + SM_VH*2 + so, vgh + (size_t)row*S_ + seg*8);
    }
    CP_COMMIT();

    float o[8][4] = {};
    float mrun[2] = {-1e30f, -1e30f};
    float lrun[2] = {0.f, 0.f};

    for (int t = 0; t < S_/64; t++) {
        const int st = t & 1;
        if (t < S_/64 - 1) {
            const int s2 = st ^ 1;
            #pragma unroll
            for (int i = 0; i < 2; i++) {
                const int idx = tid + i*256;
                const int row = idx >> 3, seg = idx & 7;
                const uint32_t so = (uint32_t)(((s2*64 + row)*TST + seg*8)*2);
                cp_async16(base + SM_KH*2 + so, kgh + (size_t)((t+1)*64+row)*DK_ + seg*8);
                cp_async16(base + SM_VH*2 + so, vgh + (size_t)row*S_ + (t+1)*64 + seg*8);
            }
            CP_COMMIT(); CP_WAIT(1);
        } else {
            CP_WAIT(0);
        }
        __syncthreads();

        const uint32_t kst  = (uint32_t)((SM_KH + st*64*TST)*2);
        const uint32_t vhst = (uint32_t)((SM_VH + st*64*TST)*2);

        // ---- S = (Q K^T)/8  = (Qh+Ql)·Kh (2-term) ---------------------------
        float s[8][4] = {};
        #pragma unroll
        for (int ks = 0; ks < 4; ks++) {
            const uint32_t qo = (uint32_t)(((wr + a_ro)*TST + ks*16 + a_co)*2);
            uint32_t ah[4], al[4];
            LDSM4(ah[0], ah[1], ah[2], ah[3], base + SM_QH*2 + qo);
            LDSM4(al[0], al[1], al[2], al[3], base + SM_QL*2 + qo);
            #pragma unroll
            for (int np = 0; np < 4; np++) {
                const uint32_t ko = (uint32_t)(((np*16 + b_ro)*TST + ks*16 + b_co)*2);
                uint32_t b0h, b1h, b2h, b3h;
                LDSM4(b0h, b1h, b2h, b3h, base + kst + ko);
                uint32_t bhA[2] = {b0h, b1h}, bhB[2] = {b2h, b3h};
                mma_f16(s[2*np  ], ah, bhA);
                mma_f16(s[2*np+1], ah, bhB);
                mma_f16(s[2*np  ], al, bhA);
                mma_f16(s[2*np+1], al, bhB);
            }
        }

        // ---- online softmax (rows g, g+8; stats across 4 c-lanes) -----------
        #pragma unroll
        for (int hf = 0; hf < 2; hf++) {
            float mx = -1e30f;
            #pragma unroll
            for (int nt = 0; nt < 8; nt++) {
                s[nt][hf*2]   *= 0.125f;
                s[nt][hf*2+1] *= 0.125f;
                mx = fmaxf(mx, fmaxf(s[nt][hf*2], s[nt][hf*2+1]));
            }
            mx = fmaxf(mx, __shfl_xor_sync(0xffffffffu, mx, 1));
            mx = fmaxf(mx, __shfl_xor_sync(0xffffffffu, mx, 2));
            const float mn = fmaxf(mrun[hf], mx);
            const float corr = __expf(mrun[hf] - mn);
            mrun[hf] = mn;
            float ls = 0.f;
            #pragma unroll
            for (int nt = 0; nt < 8; nt++) {
                const float e0 = __expf(s[nt][hf*2]   - mn);
                const float e1 = __expf(s[nt][hf*2+1] - mn);
                s[nt][hf*2] = e0; s[nt][hf*2+1] = e1;
                ls += e0 + e1;
            }
            ls += __shfl_xor_sync(0xffffffffu, ls, 1);
            ls += __shfl_xor_sync(0xffffffffu, ls, 2);
            lrun[hf] = lrun[hf]*corr + ls;
            #pragma unroll
            for (int nt = 0; nt < 8; nt++) {
                o[nt][hf*2]   *= corr;
                o[nt][hf*2+1] *= corr;
            }
        }

        // ---- P fragments directly from acc registers ------------------------
        uint32_t pa[4][4];
        #pragma unroll
        for (int kv = 0; kv < 4; kv++) {
            __half2 h0 = __floats2half2_rn(s[2*kv  ][0], s[2*kv  ][1]);
            __half2 h1 = __floats2half2_rn(s[2*kv  ][2], s[2*kv  ][3]);
            __half2 h2 = __floats2half2_rn(s[2*kv+1][0], s[2*kv+1][1]);
            __half2 h3 = __floats2half2_rn(s[2*kv+1][2], s[2*kv+1][3]);
            pa[kv][0] = *reinterpret_cast<uint32_t*>(&h0);
            pa[kv][1] = *reinterpret_cast<uint32_t*>(&h1);
            pa[kv][2] = *reinterpret_cast<uint32_t*>(&h2);
            pa[kv][3] = *reinterpret_cast<uint32_t*>(&h3);
        }

        // ---- O += P Vh (1-plane V) ------------------------------------------
        #pragma unroll
        for (int kv = 0; kv < 4; kv++) {
            #pragma unroll
            for (int np = 0; np < 4; np++) {
                const uint32_t vo = (uint32_t)(((np*16 + b_ro)*TST + kv*16 + b_co)*2);
                uint32_t v0h, v1h, v2h, v3h;
                LDSM4(v0h, v1h, v2h, v3h, base + vhst + vo);
                uint32_t vhA[2] = {v0h, v1h}, vhB[2] = {v2h, v3h};
                mma_f16(o[2*np  ], pa[kv], vhA);
                mma_f16(o[2*np+1], pa[kv], vhB);
            }
        }
        __syncthreads();
    }

    // epilogue: normalize, split, store hi/lo planes for the O-GEMM
    #pragma unroll
    for (int hf = 0; hf < 2; hf++) {
        const int r = q0 + wr + g + hf*8;
        const float inv = 1.f / lrun[hf];
        #pragma unroll
        for (int nt = 0; nt < 8; nt++) {
            const int col = h*DK_ + nt*8 + c*2;
            uint32_t h2, l2;
            split2(o[nt][hf*2]*inv, o[nt][hf*2+1]*inv, h2, l2);
            const size_t off = (((size_t)b*S_ + r)*D_ + col) >> 1;
            ((uint32_t*)g_aph)[off] = h2;
            ((uint32_t*)g_apl)[off] = l2;
        }
    }
}

// ---------------- launch ------------------------------------------------------
extern "C" void kernel_launch(void* const* d_in, const int* in_sizes, int n_in,
                              void* d_out, int out_size)
{
    (void)in_sizes; (void)n_in; (void)out_size;
    const float* Q  = (const float*)d_in[0];
    const float* K  = (const float*)d_in[1];
    const float* V  = (const float*)d_in[2];
    const float* Wq = (const float*)d_in[3];
    const float* bq = (const float*)d_in[4];
    const float* Wk = (const float*)d_in[5];
    const float* bk = (const float*)d_in[6];
    const float* Wv = (const float*)d_in[7];
    const float* bv = (const float*)d_in[8];
    const float* Wo = (const float*)d_in[9];
    const float* bo = (const float*)d_in[10];
    float* out = (float*)d_out;

    cudaFuncSetAttribute(gemm_qkv, cudaFuncAttributeMaxDynamicSharedMemorySize, GEMM_SMEM);
    cudaFuncSetAttribute(gemm_out, cudaFuncAttributeMaxDynamicSharedMemorySize, GEMM_SMEM);
    cudaFuncSetAttribute(attn_f16, cudaFuncAttributeMaxDynamicSharedMemorySize, ATTN_SMEM);

    split_all<<<dim3(4096, 7), 256>>>((const float4*)Q,  (const float4*)K,
                                      (const float4*)V,  (const float4*)Wq,
                                      (const float4*)Wk, (const float4*)Wv,
                                      (const float4*)Wo);

    gemm_qkv<<<dim3(M_/128, D_/128, 3), 128, GEMM_SMEM>>>(bq, bk, bv);

    attn_f16<<<dim3(S_/128, H_, B_), 256, ATTN_SMEM>>>();

    gemm_out<<<dim3(M_/128, D_/128), 128, GEMM_SMEM>>>(bo, out);
}

// round 15
// speedup vs baseline: 1.1031x; 1.0248x over previous
#include <cuda_runtime.h>
#include <cuda_fp16.h>
#include <math.h>
#include <stdint.h>

#define B_  2
#define S_  2048
#define D_  1024
#define H_  16
#define DK_ 64
#define M_  (B_*S_)   // 4096

// ---------------- scratch ------------------------------------------------------
__device__ __half g_qih[(size_t)M_*D_]; __device__ __half g_qil[(size_t)M_*D_];
__device__ __half g_kih[(size_t)M_*D_]; __device__ __half g_kil[(size_t)M_*D_];
__device__ __half g_vih[(size_t)M_*D_]; __device__ __half g_vil[(size_t)M_*D_];
__device__ __half g_wqh[(size_t)D_*D_];
__device__ __half g_wkh[(size_t)D_*D_];
__device__ __half g_wvh[(size_t)D_*D_];
__device__ __half g_woh[(size_t)D_*D_];
__device__ __half g_qph[(size_t)B_*H_*S_*DK_]; __device__ __half g_qpl[(size_t)B_*H_*S_*DK_];
__device__ __half g_kph[(size_t)B_*H_*S_*DK_];
__device__ __half g_vth[(size_t)B_*H_*DK_*S_];
__device__ __half g_aph[(size_t)M_*D_]; __device__ __half g_apl[(size_t)M_*D_];

// ---------------- helpers -----------------------------------------------------
__device__ __forceinline__ uint32_t smem_to_u32(const void* p) {
    uint32_t a;
    asm("{ .reg .u64 t; cvta.to.shared.u64 t, %1; cvt.u32.u64 %0, t; }"
        : "=r"(a) : "l"(p));
    return a;
}
__device__ __forceinline__ void cp_async16(uint32_t dst, const void* src) {
    asm volatile("cp.async.ca.shared.global [%0], [%1], 16;" :: "r"(dst), "l"(src));
}
#define CP_COMMIT() asm volatile("cp.async.commit_group;" ::: "memory")
#define CP_WAIT(n)  asm volatile("cp.async.wait_group %0;" :: "n"(n) : "memory")

#define LDSM4(r0,r1,r2,r3,addr) \
    asm volatile("ldmatrix.sync.aligned.m8n8.x4.shared.b16 {%0,%1,%2,%3}, [%4];" \
        : "=r"(r0),"=r"(r1),"=r"(r2),"=r"(r3) : "r"(addr))

__device__ __forceinline__ void split2(float x, float y, uint32_t& h2, uint32_t& l2) {
    __half2 hp = __floats2half2_rn(x, y);
    const float lx = x - __half2float(__low2half(hp));
    const float ly = y - __half2float(__high2half(hp));
    __half2 lp = __floats2half2_rn(lx, ly);
    h2 = *reinterpret_cast<uint32_t*>(&hp);
    l2 = *reinterpret_cast<uint32_t*>(&lp);
}

__device__ __forceinline__ void mma_f16(float* d, const uint32_t* a, const uint32_t* b) {
    asm("mma.sync.aligned.m16n8k16.row.col.f32.f16.f16.f32 "
        "{%0,%1,%2,%3}, {%4,%5,%6,%7}, {%8,%9}, {%0,%1,%2,%3};"
        : "+f"(d[0]), "+f"(d[1]), "+f"(d[2]), "+f"(d[3])
        : "r"(a[0]), "r"(a[1]), "r"(a[2]), "r"(a[3]), "r"(b[0]), "r"(b[1]));
}

// ---------------- prep: inputs hi+lo, weights hi-only, one launch -------------
__global__ __launch_bounds__(256) void split_all(
    const float4* __restrict__ q,  const float4* __restrict__ k,
    const float4* __restrict__ v,  const float4* __restrict__ wq,
    const float4* __restrict__ wk, const float4* __restrict__ wv,
    const float4* __restrict__ wo)
{
    const int t = blockIdx.y;
    const size_t i = (size_t)blockIdx.x * 256 + threadIdx.x;   // per float4
    const size_t n = (t < 3) ? (size_t)M_*D_/4 : (size_t)D_*D_/4;
    if (i >= n) return;
    const float4* src; __half *dh, *dl = nullptr;
    switch (t) {
        case 0:  src = q;  dh = g_qih; dl = g_qil; break;
        case 1:  src = k;  dh = g_kih; dl = g_kil; break;
        case 2:  src = v;  dh = g_vih; dl = g_vil; break;
        case 3:  src = wq; dh = g_wqh; break;
        case 4:  src = wk; dh = g_wkh; break;
        case 5:  src = wv; dh = g_wvh; break;
        default: src = wo; dh = g_woh; break;
    }
    const float4 x = src[i];
    uint32_t h0, l0, h1, l1;
    split2(x.x, x.y, h0, l0);
    split2(x.z, x.w, h1, l1);
    ((uint2*)dh)[i] = make_uint2(h0, h1);
    if (dl) ((uint2*)dl)[i] = make_uint2(l0, l1);
}

// ---------------- 2-term GEMM mainloop: 4 warps, warp-tile 64x64 --------------
#define AST 40                          // halves per smem row (32 + 8 pad)
#define PLANE (128*AST)                 // halves per stage-plane
#define GEMM_SMEM 69632                 // max(3 planes x 2 stages = 61440, V-tile 67584)

__device__ __forceinline__ void gemm_mainloop(
    const __half* __restrict__ Agh, const __half* __restrict__ Agl,
    const __half* __restrict__ Wgh,
    uint32_t sAh, uint32_t sAl, uint32_t sBh,
    int m0, int n0, int tid, int wm, int wn, int lane,
    float acc[4][8][4])
{
    const int lr = lane & 7;
    const int a_ro = lr + ((lane >> 3) & 1) * 8;   // A ldmatrix row offset
    const int a_co = ((lane >> 4) & 1) * 8;        // A col offset
    const int b_ro = lr + ((lane >> 4) & 1) * 8;   // B row offset
    const int b_co = ((lane >> 3) & 1) * 8;        // B col offset

    #define G_LOAD(st, chk) do { \
        _Pragma("unroll") \
        for (int i = 0; i < 4; i++) { \
            const int idx = tid + i*128, row = idx >> 2, seg = idx & 3; \
            const uint32_t so = (uint32_t)((((st)*128+row)*AST + seg*8)*2); \
            cp_async16(sAh + so, Agh + (size_t)(m0+row)*1024 + (chk)*32 + seg*8); \
            cp_async16(sAl + so, Agl + (size_t)(m0+row)*1024 + (chk)*32 + seg*8); \
            cp_async16(sBh + so, Wgh + (size_t)(n0+row)*1024 + (chk)*32 + seg*8); \
        } \
    } while (0)

    G_LOAD(0, 0); CP_COMMIT();

    for (int chk = 0; chk < 32; chk++) {
        const int st = chk & 1;
        if (chk < 31) { G_LOAD(st^1, chk+1); CP_COMMIT(); CP_WAIT(1); }
        else CP_WAIT(0);
        __syncthreads();

        const uint32_t stoff = (uint32_t)(st*PLANE*2);
        #pragma unroll
        for (int ks = 0; ks < 2; ks++) {
            uint32_t ah[4][4], al[4][4];
            #pragma unroll
            for (int mt = 0; mt < 4; mt++) {
                const uint32_t ao = stoff +
                    (uint32_t)(((wm + mt*16 + a_ro)*AST + ks*16 + a_co)*2);
                LDSM4(ah[mt][0], ah[mt][1], ah[mt][2], ah[mt][3], sAh + ao);
                LDSM4(al[mt][0], al[mt][1], al[mt][2], al[mt][3], sAl + ao);
            }
            #pragma unroll
            for (int np = 0; np < 4; np++) {
                const uint32_t bo = stoff +
                    (uint32_t)(((wn + np*16 + b_ro)*AST + ks*16 + b_co)*2);
                uint32_t b0h, b1h, b2h, b3h;
                LDSM4(b0h, b1h, b2h, b3h, sBh + bo);
                uint32_t bhA[2] = {b0h, b1h}, bhB[2] = {b2h, b3h};
                #pragma unroll
                for (int mt = 0; mt < 4; mt++) {
                    mma_f16(acc[mt][2*np  ], ah[mt], bhA);
                    mma_f16(acc[mt][2*np+1], ah[mt], bhB);
                }
                #pragma unroll
                for (int mt = 0; mt < 4; mt++) {
                    mma_f16(acc[mt][2*np  ], al[mt], bhA);
                    mma_f16(acc[mt][2*np+1], al[mt], bhB);
                }
            }
        }
        __syncthreads();
    }
    #undef G_LOAD
}

// ---------------- merged Q/K/V projection GEMM (128 threads) ------------------
__global__ __launch_bounds__(128, 2) void gemm_qkv(
    const float* __restrict__ bq, const float* __restrict__ bk,
    const float* __restrict__ bv)
{
    extern __shared__ __half smh[];
    const uint32_t base = smem_to_u32(smh);
    const uint32_t sAh = base, sAl = base + 2*PLANE*2, sBh = base + 4*PLANE*2;
    const int tid = threadIdx.x, lane = tid & 31, wid = tid >> 5;
    const int g = lane >> 2, c = lane & 3;
    const int wm = (wid & 1)*64, wn = (wid >> 1)*64;
    const int m0 = blockIdx.x*128, n0 = blockIdx.y*128;
    const int z = blockIdx.z;

    const __half *Agh, *Agl, *Wgh;
    const float* bias;
    if (z == 0) { Agh=g_qih; Agl=g_qil; Wgh=g_wqh; bias=bq; }
    else if (z == 1) { Agh=g_kih; Agl=g_kil; Wgh=g_wkh; bias=bk; }
    else { Agh=g_vih; Agl=g_vil; Wgh=g_wvh; bias=bv; }

    float acc[4][8][4] = {};
    gemm_mainloop(Agh, Agl, Wgh, sAh, sAl, sBh, m0, n0, tid, wm, wn, lane, acc);

    if (z == 0) {
        #pragma unroll
        for (int mt = 0; mt < 4; mt++)
          #pragma unroll
          for (int hf = 0; hf < 2; hf++) {
            const int m = m0 + wm + mt*16 + g + hf*8;
            const int bb = m >> 11, ss = m & (S_-1);
            #pragma unroll
            for (int nt = 0; nt < 8; nt++) {
                const int n = n0 + wn + nt*8 + c*2;
                const int hh = n >> 6, dk = n & 63;
                uint32_t h2, l2;
                split2(acc[mt][nt][hf*2+0] + bias[n],
                       acc[mt][nt][hf*2+1] + bias[n+1], h2, l2);
                const size_t o = ((((size_t)bb*H_ + hh)*S_ + ss)*DK_ + dk) >> 1;
                ((uint32_t*)g_qph)[o] = h2;
                ((uint32_t*)g_qpl)[o] = l2;
            }
          }
    } else if (z == 1) {
        #pragma unroll
        for (int mt = 0; mt < 4; mt++)
          #pragma unroll
          for (int hf = 0; hf < 2; hf++) {
            const int m = m0 + wm + mt*16 + g + hf*8;
            const int bb = m >> 11, ss = m & (S_-1);
            #pragma unroll
            for (int nt = 0; nt < 8; nt++) {
                const int n = n0 + wn + nt*8 + c*2;
                const int hh = n >> 6, dk = n & 63;
                const __half2 hp = __floats2half2_rn(acc[mt][nt][hf*2+0] + bias[n],
                                                     acc[mt][nt][hf*2+1] + bias[n+1]);
                const size_t o = ((((size_t)bb*H_ + hh)*S_ + ss)*DK_ + dk) >> 1;
                ((__half2*)g_kph)[o] = hp;
            }
          }
    } else {
        float* tile = (float*)smh;   // [128 n][132]
        __syncthreads();
        #pragma unroll
        for (int mt = 0; mt < 4; mt++)
          #pragma unroll
          for (int hf = 0; hf < 2; hf++) {
            const int ml = wm + mt*16 + g + hf*8;
            #pragma unroll
            for (int nt = 0; nt < 8; nt++) {
                const int nl = wn + nt*8 + c*2;
                tile[(nl  )*132 + ml] = acc[mt][nt][hf*2+0] + bias[n0+nl];
                tile[(nl+1)*132 + ml] = acc[mt][nt][hf*2+1] + bias[n0+nl+1];
            }
          }
        __syncthreads();
        const int bb = m0 >> 11, s0 = m0 & (S_-1);
        #pragma unroll
        for (int i = 0; i < 64; i++) {
            const int idx = tid + i*128;      // 0..8191
            const int nl = idx >> 6;          // 0..127
            const int sp = idx & 63;          // 0..63 (s-pair)
            const int hh = (n0 + nl) >> 6, dk = (n0 + nl) & 63;
            const __half2 hp = __floats2half2_rn(tile[nl*132 + 2*sp],
                                                 tile[nl*132 + 2*sp + 1]);
            const size_t o = ((((size_t)bb*H_ + hh)*DK_ + dk)*S_ + s0 + 2*sp) >> 1;
            ((__half2*)g_vth)[o] = hp;
        }
    }
}

// ---------------- output GEMM (128 threads) -----------------------------------
__global__ __launch_bounds__(128, 2) void gemm_out(const float* __restrict__ bias,
                                                   float* __restrict__ C)
{
    extern __shared__ __half smh[];
    const uint32_t base = smem_to_u32(smh);
    const uint32_t sAh = base, sAl = base + 2*PLANE*2, sBh = base + 4*PLANE*2;
    const int tid = threadIdx.x, lane = tid & 31, wid = tid >> 5;
    const int g = lane >> 2, c = lane & 3;
    const int wm = (wid & 1)*64, wn = (wid >> 1)*64;
    const int m0 = blockIdx.x*128, n0 = blockIdx.y*128;

    float acc[4][8][4] = {};
    gemm_mainloop(g_aph, g_apl, g_woh, sAh, sAl, sBh, m0, n0, tid, wm, wn, lane, acc);

    #pragma unroll
    for (int mt = 0; mt < 4; mt++)
      #pragma unroll
      for (int hf = 0; hf < 2; hf++) {
        const int m = m0 + wm + mt*16 + g + hf*8;
        #pragma unroll
        for (int nt = 0; nt < 8; nt++) {
            const int n = n0 + wn + nt*8 + c*2;
            *(float2*)(C + (size_t)m*D_ + n) =
                make_float2(acc[mt][nt][hf*2+0] + bias[n],
                            acc[mt][nt][hf*2+1] + bias[n+1]);
        }
      }
}

// ---------------- fp16 flash attention: 4 warps x 32 q-rows -------------------
#define TST 72                          // halves per smem row (64 + 8 pad)
#define SM_QH 0
#define SM_QL (128*TST)
#define SM_KH (2*128*TST)
#define SM_VH (SM_KH + 2*64*TST)
#define ATTN_SMEM ((SM_VH + 2*64*TST)*2)   // 73728 B

__global__ __launch_bounds__(128, 2) void attn_f16()
{
    extern __shared__ __half smh[];
    const uint32_t base = smem_to_u32(smh);
    const int tid = threadIdx.x, lane = tid & 31, wid = tid >> 5;
    const int g = lane >> 2, c = lane & 3;
    const int wr = wid * 32;                 // 4 warps x 32 q-rows
    const int h = blockIdx.y, b = blockIdx.z;
    const int q0 = blockIdx.x * 128;
    const size_t bh = (size_t)b*H_ + h;
    const __half* qgh = g_qph + (bh*S_ + q0)*DK_;
    const __half* qgl = g_qpl + (bh*S_ + q0)*DK_;
    const __half* kgh = g_kph + bh*S_*DK_;
    const __half* vgh = g_vth + bh*DK_*S_;

    const int lr = lane & 7;
    const int a_ro = lr + ((lane >> 3) & 1) * 8;
    const int a_co = ((lane >> 4) & 1) * 8;
    const int b_ro = lr + ((lane >> 4) & 1) * 8;
    const int b_co = ((lane >> 3) & 1) * 8;

    // prologue: Q planes + K/V tile 0
    #pragma unroll
    for (int i = 0; i < 8; i++) {
        const int idx = tid + i*128;          // 0..1023
        const int row = idx >> 3, seg = idx & 7;
        const uint32_t so = (uint32_t)((row*TST + seg*8)*2);
        cp_async16(base + SM_QH*2 + so, qgh + (size_t)row*DK_ + seg*8);
        cp_async16(base + SM_QL*2 + so, qgl + (size_t)row*DK_ + seg*8);
    }
    #pragma unroll
    for (int i = 0; i < 4; i++) {
        const int idx = tid + i*128;          // 0..511
        const int row = idx >> 3, seg = idx & 7;
        const uint32_t so = (uint32_t)((row*TST + seg*8)*2);
        cp_async16(base + SM_KH*2 + so, kgh + (size_t)row*DK_ + seg*8);
        cp_async16(base + SM_VH*2 + so, vgh + (size_t)row*S_ + seg*8);
    }
    CP_COMMIT();

    float o[2][8][4] = {};
    float mrun[2][2] = {{-1e30f,-1e30f},{-1e30f,-1e30f}};
    float lrun[2][2] = {{0.f,0.f},{0.f,0.f}};

    for (int t = 0; t < S_/64; t++) {
        const int st = t & 1;
        if (t < S_/64 - 1) {
            const int s2 = st ^ 1;
            #pragma unroll
            for (int i = 0; i < 4; i++) {
                const int idx = tid + i*128;
                const int row = idx >> 3, seg = idx & 7;
                const uint32_t so = (uint32_t)(((s2*64 + row)*TST + seg*8)*2);
                cp_async16(base + SM_KH*2 + so, kgh + (size_t)((t+1)*64+row)*DK_ + seg*8);
                cp_async16(base + SM_VH*2 + so, vgh + (size_t)row*S_ + (t+1)*64 + seg*8);
            }
            CP_COMMIT(); CP_WAIT(1);
        } else {
            CP_WAIT(0);
        }
        __syncthreads();

        const uint32_t kst  = (uint32_t)((SM_KH + st*64*TST)*2);
        const uint32_t vhst = (uint32_t)((SM_VH + st*64*TST)*2);

        // ---- S = (Q K^T)/8  = (Qh+Ql)·Kh, 2 m-subtiles ----------------------
        float s[2][8][4] = {};
        #pragma unroll
        for (int ks = 0; ks < 4; ks++) {
            uint32_t ah[2][4], al[2][4];
            #pragma unroll
            for (int mt = 0; mt < 2; mt++) {
                const uint32_t qo =
                    (uint32_t)(((wr + mt*16 + a_ro)*TST + ks*16 + a_co)*2);
                LDSM4(ah[mt][0], ah[mt][1], ah[mt][2], ah[mt][3], base + SM_QH*2 + qo);
                LDSM4(al[mt][0], al[mt][1], al[mt][2], al[mt][3], base + SM_QL*2 + qo);
            }
            #pragma unroll
            for (int np = 0; np < 4; np++) {
                const uint32_t ko = (uint32_t)(((np*16 + b_ro)*TST + ks*16 + b_co)*2);
                uint32_t b0h, b1h, b2h, b3h;
                LDSM4(b0h, b1h, b2h, b3h, base + kst + ko);
                uint32_t bhA[2] = {b0h, b1h}, bhB[2] = {b2h, b3h};
                #pragma unroll
                for (int mt = 0; mt < 2; mt++) {
                    mma_f16(s[mt][2*np  ], ah[mt], bhA);
                    mma_f16(s[mt][2*np+1], ah[mt], bhB);
                }
                #pragma unroll
                for (int mt = 0; mt < 2; mt++) {
                    mma_f16(s[mt][2*np  ], al[mt], bhA);
                    mma_f16(s[mt][2*np+1], al[mt], bhB);
                }
            }
        }

        // ---- online softmax (per mt: rows g, g+8; stats across 4 c-lanes) ---
        #pragma unroll
        for (int mt = 0; mt < 2; mt++)
          #pragma unroll
          for (int hf = 0; hf < 2; hf++) {
            float mx = -1e30f;
            #pragma unroll
            for (int nt = 0; nt < 8; nt++) {
                s[mt][nt][hf*2]   *= 0.125f;
                s[mt][nt][hf*2+1] *= 0.125f;
                mx = fmaxf(mx, fmaxf(s[mt][nt][hf*2], s[mt][nt][hf*2+1]));
            }
            mx = fmaxf(mx, __shfl_xor_sync(0xffffffffu, mx, 1));
            mx = fmaxf(mx, __shfl_xor_sync(0xffffffffu, mx, 2));
            const float mn = fmaxf(mrun[mt][hf], mx);
            const float corr = __expf(mrun[mt][hf] - mn);
            mrun[mt][hf] = mn;
            float ls = 0.f;
            #pragma unroll
            for (int nt = 0; nt < 8; nt++) {
                const float e0 = __expf(s[mt][nt][hf*2]   - mn);
                const float e1 = __expf(s[mt][nt][hf*2+1] - mn);
                s[mt][nt][hf*2] = e0; s[mt][nt][hf*2+1] = e1;
                ls += e0 + e1;
            }
            ls += __shfl_xor_sync(0xffffffffu, ls, 1);
            ls += __shfl_xor_sync(0xffffffffu, ls, 2);
            lrun[mt][hf] = lrun[mt][hf]*corr + ls;
            #pragma unroll
            for (int nt = 0; nt < 8; nt++) {
                o[mt][nt][hf*2]   *= corr;
                o[mt][nt][hf*2+1] *= corr;
            }
          }

        // ---- P fragments directly from acc registers ------------------------
        uint32_t pa[2][4][4];
        #pragma unroll
        for (int mt = 0; mt < 2; mt++)
          #pragma unroll
          for (int kv = 0; kv < 4; kv++) {
            __half2 h0 = __floats2half2_rn(s[mt][2*kv  ][0], s[mt][2*kv  ][1]);
            __half2 h1 = __floats2half2_rn(s[mt][2*kv  ][2], s[mt][2*kv  ][3]);
            __half2 h2 = __floats2half2_rn(s[mt][2*kv+1][0], s[mt][2*kv+1][1]);
            __half2 h3 = __floats2half2_rn(s[mt][2*kv+1][2], s[mt][2*kv+1][3]);
            pa[mt][kv][0] = *reinterpret_cast<uint32_t*>(&h0);
            pa[mt][kv][1] = *reinterpret_cast<uint32_t*>(&h1);
            pa[mt][kv][2] = *reinterpret_cast<uint32_t*>(&h2);
            pa[mt][kv][3] = *reinterpret_cast<uint32_t*>(&h3);
          }

        // ---- O += P Vh (V fragments reused across 2 m-subtiles) -------------
        #pragma unroll
        for (int kv = 0; kv < 4; kv++) {
            #pragma unroll
            for (int np = 0; np < 4; np++) {
                const uint32_t vo = (uint32_t)(((np*16 + b_ro)*TST + kv*16 + b_co)*2);
                uint32_t v0h, v1h, v2h, v3h;
                LDSM4(v0h, v1h, v2h, v3h, base + vhst + vo);
                uint32_t vhA[2] = {v0h, v1h}, vhB[2] = {v2h, v3h};
                #pragma unroll
                for (int mt = 0; mt < 2; mt++) {
                    mma_f16(o[mt][2*np  ], pa[mt][kv], vhA);
                    mma_f16(o[mt][2*np+1], pa[mt][kv], vhB);
                }
            }
        }
        __syncthreads();
    }

    // epilogue: normalize, split, store hi/lo planes for the O-GEMM
    #pragma unroll
    for (int mt = 0; mt < 2; mt++)
      #pragma unroll
      for (int hf = 0; hf < 2; hf++) {
        const int r = q0 + wr + mt*16 + g + hf*8;
        const float inv = 1.f / lrun[mt][hf];
        #pragma unroll
        for (int nt = 0; nt < 8; nt++) {
            const int col = h*DK_ + nt*8 + c*2;
            uint32_t h2, l2;
            split2(o[mt][nt][hf*2]*inv, o[mt][nt][hf*2+1]*inv, h2, l2);
            const size_t off = (((size_t)b*S_ + r)*D_ + col) >> 1;
            ((uint32_t*)g_aph)[off] = h2;
            ((uint32_t*)g_apl)[off] = l2;
        }
      }
}

// ---------------- launch ------------------------------------------------------
extern "C" void kernel_launch(void* const* d_in, const int* in_sizes, int n_in,
                              void* d_out, int out_size)
{
    (void)in_sizes; (void)n_in; (void)out_size;
    const float* Q  = (const float*)d_in[0];
    const float* K  = (const float*)d_in[1];
    const float* V  = (const float*)d_in[2];
    const float* Wq = (const float*)d_in[3];
    const float* bq = (const float*)d_in[4];
    const float* Wk = (const float*)d_in[5];
    const float* bk = (const float*)d_in[6];
    const float* Wv = (const float*)d_in[7];
    const float* bv = (const float*)d_in[8];
    const float* Wo = (const float*)d_in[9];
    const float* bo = (const float*)d_in[10];
    float* out = (float*)d_out;

    cudaFuncSetAttribute(gemm_qkv, cudaFuncAttributeMaxDynamicSharedMemorySize, GEMM_SMEM);
    cudaFuncSetAttribute(gemm_out, cudaFuncAttributeMaxDynamicSharedMemorySize, GEMM_SMEM);
    cudaFuncSetAttribute(attn_f16, cudaFuncAttributeMaxDynamicSharedMemorySize, ATTN_SMEM);

    split_all<<<dim3(4096, 7), 256>>>((const float4*)Q,  (const float4*)K,
                                      (const float4*)V,  (const float4*)Wq,
                                      (const float4*)Wk, (const float4*)Wv,
                                      (const float4*)Wo);

    gemm_qkv<<<dim3(M_/128, D_/128, 3), 128, GEMM_SMEM>>>(bq, bk, bv);

    attn_f16<<<dim3(S_/128, H_, B_), 128, ATTN_SMEM>>>();

    gemm_out<<<dim3(M_/128, D_/128), 128, GEMM_SMEM>>>(bo, out);
}

// round 16
// speedup vs baseline: 1.1140x; 1.0099x over previous
#include <cuda_runtime.h>
#include <cuda_fp16.h>
#include <math.h>
#include <stdint.h>

#define B_  2
#define S_  2048
#define D_  1024
#define H_  16
#define DK_ 64
#define M_  (B_*S_)   // 4096

// ---------------- scratch ------------------------------------------------------
__device__ __half g_qih[(size_t)M_*D_]; __device__ __half g_qil[(size_t)M_*D_];
__device__ __half g_kih[(size_t)M_*D_]; __device__ __half g_kil[(size_t)M_*D_];
__device__ __half g_vih[(size_t)M_*D_]; __device__ __half g_vil[(size_t)M_*D_];
__device__ __half g_wqh[(size_t)D_*D_];
__device__ __half g_wkh[(size_t)D_*D_];
__device__ __half g_wvh[(size_t)D_*D_];
__device__ __half g_woh[(size_t)D_*D_];
__device__ __half g_qph[(size_t)B_*H_*S_*DK_]; __device__ __half g_qpl[(size_t)B_*H_*S_*DK_];
__device__ __half g_kph[(size_t)B_*H_*S_*DK_];
__device__ __half g_vth[(size_t)B_*H_*DK_*S_];
__device__ __half g_aph[(size_t)M_*D_]; __device__ __half g_apl[(size_t)M_*D_];

// ---------------- helpers -----------------------------------------------------
__device__ __forceinline__ uint32_t smem_to_u32(const void* p) {
    uint32_t a;
    asm("{ .reg .u64 t; cvta.to.shared.u64 t, %1; cvt.u32.u64 %0, t; }"
        : "=r"(a) : "l"(p));
    return a;
}
__device__ __forceinline__ void cp_async16(uint32_t dst, const void* src) {
    asm volatile("cp.async.ca.shared.global [%0], [%1], 16;" :: "r"(dst), "l"(src));
}
#define CP_COMMIT() asm volatile("cp.async.commit_group;" ::: "memory")
#define CP_WAIT(n)  asm volatile("cp.async.wait_group %0;" :: "n"(n) : "memory")

#define LDSM4(r0,r1,r2,r3,addr) \
    asm volatile("ldmatrix.sync.aligned.m8n8.x4.shared.b16 {%0,%1,%2,%3}, [%4];" \
        : "=r"(r0),"=r"(r1),"=r"(r2),"=r"(r3) : "r"(addr))

__device__ __forceinline__ void split2(float x, float y, uint32_t& h2, uint32_t& l2) {
    __half2 hp = __floats2half2_rn(x, y);
    const float lx = x - __half2float(__low2half(hp));
    const float ly = y - __half2float(__high2half(hp));
    __half2 lp = __floats2half2_rn(lx, ly);
    h2 = *reinterpret_cast<uint32_t*>(&hp);
    l2 = *reinterpret_cast<uint32_t*>(&lp);
}

__device__ __forceinline__ void mma_f16(float* d, const uint32_t* a, const uint32_t* b) {
    asm("mma.sync.aligned.m16n8k16.row.col.f32.f16.f16.f32 "
        "{%0,%1,%2,%3}, {%4,%5,%6,%7}, {%8,%9}, {%0,%1,%2,%3};"
        : "+f"(d[0]), "+f"(d[1]), "+f"(d[2]), "+f"(d[3])
        : "r"(a[0]), "r"(a[1]), "r"(a[2]), "r"(a[3]), "r"(b[0]), "r"(b[1]));
}

// ---------------- prep: inputs hi+lo, weights hi-only, one launch -------------
__global__ __launch_bounds__(256) void split_all(
    const float4* __restrict__ q,  const float4* __restrict__ k,
    const float4* __restrict__ v,  const float4* __restrict__ wq,
    const float4* __restrict__ wk, const float4* __restrict__ wv,
    const float4* __restrict__ wo)
{
    const int t = blockIdx.y;
    const size_t i = (size_t)blockIdx.x * 256 + threadIdx.x;   // per float4
    const size_t n = (t < 3) ? (size_t)M_*D_/4 : (size_t)D_*D_/4;
    if (i >= n) return;
    const float4* src; __half *dh, *dl = nullptr;
    switch (t) {
        case 0:  src = q;  dh = g_qih; dl = g_qil; break;
        case 1:  src = k;  dh = g_kih; dl = g_kil; break;
        case 2:  src = v;  dh = g_vih; dl = g_vil; break;
        case 3:  src = wq; dh = g_wqh; break;
        case 4:  src = wk; dh = g_wkh; break;
        case 5:  src = wv; dh = g_wvh; break;
        default: src = wo; dh = g_woh; break;
    }
    const float4 x = src[i];
    uint32_t h0, l0, h1, l1;
    split2(x.x, x.y, h0, l0);
    split2(x.z, x.w, h1, l1);
    ((uint2*)dh)[i] = make_uint2(h0, h1);
    if (dl) ((uint2*)dl)[i] = make_uint2(l0, l1);
}

// ---------------- 2-term GEMM mainloop: 4 warps, warp-tile 64x64 --------------
#define AST 40                          // halves per smem row (32 + 8 pad)
#define PLANE (128*AST)                 // halves per stage-plane
#define GEMM_SMEM 69632                 // max(3 planes x 2 stages = 61440, V-tile 67584)

__device__ __forceinline__ void gemm_mainloop(
    const __half* __restrict__ Agh, const __half* __restrict__ Agl,
    const __half* __restrict__ Wgh,
    uint32_t sAh, uint32_t sAl, uint32_t sBh,
    int m0, int n0, int tid, int wm, int wn, int lane,
    float acc[4][8][4])
{
    const int lr = lane & 7;
    const int a_ro = lr + ((lane >> 3) & 1) * 8;   // A ldmatrix row offset
    const int a_co = ((lane >> 4) & 1) * 8;        // A col offset
    const int b_ro = lr + ((lane >> 4) & 1) * 8;   // B row offset
    const int b_co = ((lane >> 3) & 1) * 8;        // B col offset

    #define G_LOAD(st, chk) do { \
        _Pragma("unroll") \
        for (int i = 0; i < 4; i++) { \
            const int idx = tid + i*128, row = idx >> 2, seg = idx & 3; \
            const uint32_t so = (uint32_t)((((st)*128+row)*AST + seg*8)*2); \
            cp_async16(sAh + so, Agh + (size_t)(m0+row)*1024 + (chk)*32 + seg*8); \
            cp_async16(sAl + so, Agl + (size_t)(m0+row)*1024 + (chk)*32 + seg*8); \
            cp_async16(sBh + so, Wgh + (size_t)(n0+row)*1024 + (chk)*32 + seg*8); \
        } \
    } while (0)

    G_LOAD(0, 0); CP_COMMIT();

    for (int chk = 0; chk < 32; chk++) {
        const int st = chk & 1;
        if (chk < 31) { G_LOAD(st^1, chk+1); CP_COMMIT(); CP_WAIT(1); }
        else CP_WAIT(0);
        __syncthreads();

        const uint32_t stoff = (uint32_t)(st*PLANE*2);
        #pragma unroll
        for (int ks = 0; ks < 2; ks++) {
            uint32_t ah[4][4], al[4][4];
            #pragma unroll
            for (int mt = 0; mt < 4; mt++) {
                const uint32_t ao = stoff +
                    (uint32_t)(((wm + mt*16 + a_ro)*AST + ks*16 + a_co)*2);
                LDSM4(ah[mt][0], ah[mt][1], ah[mt][2], ah[mt][3], sAh + ao);
                LDSM4(al[mt][0], al[mt][1], al[mt][2], al[mt][3], sAl + ao);
            }
            #pragma unroll
            for (int np = 0; np < 4; np++) {
                const uint32_t bo = stoff +
                    (uint32_t)(((wn + np*16 + b_ro)*AST + ks*16 + b_co)*2);
                uint32_t b0h, b1h, b2h, b3h;
                LDSM4(b0h, b1h, b2h, b3h, sBh + bo);
                uint32_t bhA[2] = {b0h, b1h}, bhB[2] = {b2h, b3h};
                #pragma unroll
                for (int mt = 0; mt < 4; mt++) {
                    mma_f16(acc[mt][2*np  ], ah[mt], bhA);
                    mma_f16(acc[mt][2*np+1], ah[mt], bhB);
                }
                #pragma unroll
                for (int mt = 0; mt < 4; mt++) {
                    mma_f16(acc[mt][2*np  ], al[mt], bhA);
                    mma_f16(acc[mt][2*np+1], al[mt], bhB);
                }
            }
        }
        __syncthreads();
    }
    #undef G_LOAD
}

// ---------------- merged Q/K/V projection GEMM (128 threads) ------------------
__global__ __launch_bounds__(128, 2) void gemm_qkv(
    const float* __restrict__ bq, const float* __restrict__ bk,
    const float* __restrict__ bv)
{
    extern __shared__ __half smh[];
    const uint32_t base = smem_to_u32(smh);
    const uint32_t sAh = base, sAl = base + 2*PLANE*2, sBh = base + 4*PLANE*2;
    const int tid = threadIdx.x, lane = tid & 31, wid = tid >> 5;
    const int g = lane >> 2, c = lane & 3;
    const int wm = (wid & 1)*64, wn = (wid >> 1)*64;
    const int m0 = blockIdx.x*128, n0 = blockIdx.y*128;
    const int z = blockIdx.z;

    const __half *Agh, *Agl, *Wgh;
    const float* bias;
    if (z == 0) { Agh=g_qih; Agl=g_qil; Wgh=g_wqh; bias=bq; }
    else if (z == 1) { Agh=g_kih; Agl=g_kil; Wgh=g_wkh; bias=bk; }
    else { Agh=g_vih; Agl=g_vil; Wgh=g_wvh; bias=bv; }

    float acc[4][8][4] = {};
    gemm_mainloop(Agh, Agl, Wgh, sAh, sAl, sBh, m0, n0, tid, wm, wn, lane, acc);

    if (z == 0) {
        #pragma unroll
        for (int mt = 0; mt < 4; mt++)
          #pragma unroll
          for (int hf = 0; hf < 2; hf++) {
            const int m = m0 + wm + mt*16 + g + hf*8;
            const int bb = m >> 11, ss = m & (S_-1);
            #pragma unroll
            for (int nt = 0; nt < 8; nt++) {
                const int n = n0 + wn + nt*8 + c*2;
                const int hh = n >> 6, dk = n & 63;
                uint32_t h2, l2;
                split2(acc[mt][nt][hf*2+0] + bias[n],
                       acc[mt][nt][hf*2+1] + bias[n+1], h2, l2);
                const size_t o = ((((size_t)bb*H_ + hh)*S_ + ss)*DK_ + dk) >> 1;
                ((uint32_t*)g_qph)[o] = h2;
                ((uint32_t*)g_qpl)[o] = l2;
            }
          }
    } else if (z == 1) {
        #pragma unroll
        for (int mt = 0; mt < 4; mt++)
          #pragma unroll
          for (int hf = 0; hf < 2; hf++) {
            const int m = m0 + wm + mt*16 + g + hf*8;
            const int bb = m >> 11, ss = m & (S_-1);
            #pragma unroll
            for (int nt = 0; nt < 8; nt++) {
                const int n = n0 + wn + nt*8 + c*2;
                const int hh = n >> 6, dk = n & 63;
                const __half2 hp = __floats2half2_rn(acc[mt][nt][hf*2+0] + bias[n],
                                                     acc[mt][nt][hf*2+1] + bias[n+1]);
                const size_t o = ((((size_t)bb*H_ + hh)*S_ + ss)*DK_ + dk) >> 1;
                ((__half2*)g_kph)[o] = hp;
            }
          }
    } else {
        float* tile = (float*)smh;   // [128 n][132]
        __syncthreads();
        #pragma unroll
        for (int mt = 0; mt < 4; mt++)
          #pragma unroll
          for (int hf = 0; hf < 2; hf++) {
            const int ml = wm + mt*16 + g + hf*8;
            #pragma unroll
            for (int nt = 0; nt < 8; nt++) {
                const int nl = wn + nt*8 + c*2;
                tile[(nl  )*132 + ml] = acc[mt][nt][hf*2+0] + bias[n0+nl];
                tile[(nl+1)*132 + ml] = acc[mt][nt][hf*2+1] + bias[n0+nl+1];
            }
          }
        __syncthreads();
        const int bb = m0 >> 11, s0 = m0 & (S_-1);
        #pragma unroll
        for (int i = 0; i < 64; i++) {
            const int idx = tid + i*128;      // 0..8191
            const int nl = idx >> 6;          // 0..127
            const int sp = idx & 63;          // 0..63 (s-pair)
            const int hh = (n0 + nl) >> 6, dk = (n0 + nl) & 63;
            const __half2 hp = __floats2half2_rn(tile[nl*132 + 2*sp],
                                                 tile[nl*132 + 2*sp + 1]);
            const size_t o = ((((size_t)bb*H_ + hh)*DK_ + dk)*S_ + s0 + 2*sp) >> 1;
            ((__half2*)g_vth)[o] = hp;
        }
    }
}

// ---------------- output GEMM (128 threads) -----------------------------------
__global__ __launch_bounds__(128, 2) void gemm_out(const float* __restrict__ bias,
                                                   float* __restrict__ C)
{
    extern __shared__ __half smh[];
    const uint32_t base = smem_to_u32(smh);
    const uint32_t sAh = base, sAl = base + 2*PLANE*2, sBh = base + 4*PLANE*2;
    const int tid = threadIdx.x, lane = tid & 31, wid = tid >> 5;
    const int g = lane >> 2, c = lane & 3;
    const int wm = (wid & 1)*64, wn = (wid >> 1)*64;
    const int m0 = blockIdx.x*128, n0 = blockIdx.y*128;

    float acc[4][8][4] = {};
    gemm_mainloop(g_aph, g_apl, g_woh, sAh, sAl, sBh, m0, n0, tid, wm, wn, lane, acc);

    #pragma unroll
    for (int mt = 0; mt < 4; mt++)
      #pragma unroll
      for (int hf = 0; hf < 2; hf++) {
        const int m = m0 + wm + mt*16 + g + hf*8;
        #pragma unroll
        for (int nt = 0; nt < 8; nt++) {
            const int n = n0 + wn + nt*8 + c*2;
            *(float2*)(C + (size_t)m*D_ + n) =
                make_float2(acc[mt][nt][hf*2+0] + bias[n],
                            acc[mt][nt][hf*2+1] + bias[n+1]);
        }
      }
}

// ---------------- fp16 flash attention: 4 warps x 32 q-rows, Q in regs --------
#define TST 72                          // halves per smem row (64 + 8 pad)
#define SM_QH 0
#define SM_QL (128*TST)
#define SM_KH (2*128*TST)
#define SM_VH (SM_KH + 2*64*TST)
#define ATTN_SMEM ((SM_VH + 2*64*TST)*2)   // 73728 B

__global__ __launch_bounds__(128, 2) void attn_f16()
{
    extern __shared__ __half smh[];
    const uint32_t base = smem_to_u32(smh);
    const int tid = threadIdx.x, lane = tid & 31, wid = tid >> 5;
    const int g = lane >> 2, c = lane & 3;
    const int wr = wid * 32;                 // 4 warps x 32 q-rows
    const int h = blockIdx.y, b = blockIdx.z;
    const int q0 = blockIdx.x * 128;
    const size_t bh = (size_t)b*H_ + h;
    const __half* qgh = g_qph + (bh*S_ + q0)*DK_;
    const __half* qgl = g_qpl + (bh*S_ + q0)*DK_;
    const __half* kgh = g_kph + bh*S_*DK_;
    const __half* vgh = g_vth + bh*DK_*S_;

    const int lr = lane & 7;
    const int a_ro = lr + ((lane >> 3) & 1) * 8;
    const int a_co = ((lane >> 4) & 1) * 8;
    const int b_ro = lr + ((lane >> 4) & 1) * 8;
    const int b_co = ((lane >> 3) & 1) * 8;

    // prologue: Q planes + K/V tile 0
    #pragma unroll
    for (int i = 0; i < 8; i++) {
        const int idx = tid + i*128;          // 0..1023
        const int row = idx >> 3, seg = idx & 7;
        const uint32_t so = (uint32_t)((row*TST + seg*8)*2);
        cp_async16(base + SM_QH*2 + so, qgh + (size_t)row*DK_ + seg*8);
        cp_async16(base + SM_QL*2 + so, qgl + (size_t)row*DK_ + seg*8);
    }
    #pragma unroll
    for (int i = 0; i < 4; i++) {
        const int idx = tid + i*128;          // 0..511
        const int row = idx >> 3, seg = idx & 7;
        const uint32_t so = (uint32_t)((row*TST + seg*8)*2);
        cp_async16(base + SM_KH*2 + so, kgh + (size_t)row*DK_ + seg*8);
        cp_async16(base + SM_VH*2 + so, vgh + (size_t)row*S_ + seg*8);
    }
    CP_COMMIT();

    // Q fragments cached in registers for the whole mainloop (loaded at t=0)
    uint32_t qfh[2][4][4], qfl[2][4][4];

    float o[2][8][4] = {};
    float mrun[2][2] = {{-1e30f,-1e30f},{-1e30f,-1e30f}};
    float lrun[2][2] = {{0.f,0.f},{0.f,0.f}};

    for (int t = 0; t < S_/64; t++) {
        const int st = t & 1;
        if (t < S_/64 - 1) {
            const int s2 = st ^ 1;
            #pragma unroll
            for (int i = 0; i < 4; i++) {
                const int idx = tid + i*128;
                const int row = idx >> 3, seg = idx & 7;
                const uint32_t so = (uint32_t)(((s2*64 + row)*TST + seg*8)*2);
                cp_async16(base + SM_KH*2 + so, kgh + (size_t)((t+1)*64+row)*DK_ + seg*8);
                cp_async16(base + SM_VH*2 + so, vgh + (size_t)row*S_ + (t+1)*64 + seg*8);
            }
            CP_COMMIT(); CP_WAIT(1);
        } else {
            CP_WAIT(0);
        }
        __syncthreads();

        if (t == 0) {
            // one-time Q fragment load into registers
            #pragma unroll
            for (int mt = 0; mt < 2; mt++)
                #pragma unroll
                for (int ks = 0; ks < 4; ks++) {
                    const uint32_t qo =
                        (uint32_t)(((wr + mt*16 + a_ro)*TST + ks*16 + a_co)*2);
                    LDSM4(qfh[mt][ks][0], qfh[mt][ks][1], qfh[mt][ks][2], qfh[mt][ks][3],
                          base + SM_QH*2 + qo);
                    LDSM4(qfl[mt][ks][0], qfl[mt][ks][1], qfl[mt][ks][2], qfl[mt][ks][3],
                          base + SM_QL*2 + qo);
                }
        }

        const uint32_t kst  = (uint32_t)((SM_KH + st*64*TST)*2);
        const uint32_t vhst = (uint32_t)((SM_VH + st*64*TST)*2);

        // ---- S = (Q K^T)/8  = (Qh+Ql)·Kh, Q from registers ------------------
        float s[2][8][4] = {};
        #pragma unroll
        for (int ks = 0; ks < 4; ks++) {
            #pragma unroll
            for (int np = 0; np < 4; np++) {
                const uint32_t ko = (uint32_t)(((np*16 + b_ro)*TST + ks*16 + b_co)*2);
                uint32_t b0h, b1h, b2h, b3h;
                LDSM4(b0h, b1h, b2h, b3h, base + kst + ko);
                uint32_t bhA[2] = {b0h, b1h}, bhB[2] = {b2h, b3h};
                #pragma unroll
                for (int mt = 0; mt < 2; mt++) {
                    mma_f16(s[mt][2*np  ], qfh[mt][ks], bhA);
                    mma_f16(s[mt][2*np+1], qfh[mt][ks], bhB);
                }
                #pragma unroll
                for (int mt = 0; mt < 2; mt++) {
                    mma_f16(s[mt][2*np  ], qfl[mt][ks], bhA);
                    mma_f16(s[mt][2*np+1], qfl[mt][ks], bhB);
                }
            }
        }

        // ---- online softmax (per mt: rows g, g+8; stats across 4 c-lanes) ---
        #pragma unroll
        for (int mt = 0; mt < 2; mt++)
          #pragma unroll
          for (int hf = 0; hf < 2; hf++) {
            float mx = -1e30f;
            #pragma unroll
            for (int nt = 0; nt < 8; nt++) {
                s[mt][nt][hf*2]   *= 0.125f;
                s[mt][nt][hf*2+1] *= 0.125f;
                mx = fmaxf(mx, fmaxf(s[mt][nt][hf*2], s[mt][nt][hf*2+1]));
            }
            mx = fmaxf(mx, __shfl_xor_sync(0xffffffffu, mx, 1));
            mx = fmaxf(mx, __shfl_xor_sync(0xffffffffu, mx, 2));
            const float mn = fmaxf(mrun[mt][hf], mx);
            const float corr = __expf(mrun[mt][hf] - mn);
            mrun[mt][hf] = mn;
            float ls = 0.f;
            #pragma unroll
            for (int nt = 0; nt < 8; nt++) {
                const float e0 = __expf(s[mt][nt][hf*2]   - mn);
                const float e1 = __expf(s[mt][nt][hf*2+1] - mn);
                s[mt][nt][hf*2] = e0; s[mt][nt][hf*2+1] = e1;
                ls += e0 + e1;
            }
            ls += __shfl_xor_sync(0xffffffffu, ls, 1);
            ls += __shfl_xor_sync(0xffffffffu, ls, 2);
            lrun[mt][hf] = lrun[mt][hf]*corr + ls;
            #pragma unroll
            for (int nt = 0; nt < 8; nt++) {
                o[mt][nt][hf*2]   *= corr;
                o[mt][nt][hf*2+1] *= corr;
            }
          }

        // ---- P fragments directly from acc registers ------------------------
        uint32_t pa[2][4][4];
        #pragma unroll
        for (int mt = 0; mt < 2; mt++)
          #pragma unroll
          for (int kv = 0; kv < 4; kv++) {
            __half2 h0 = __floats2half2_rn(s[mt][2*kv  ][0], s[mt][2*kv  ][1]);
            __half2 h1 = __floats2half2_rn(s[mt][2*kv  ][2], s[mt][2*kv  ][3]);
            __half2 h2 = __floats2half2_rn(s[mt][2*kv+1][0], s[mt][2*kv+1][1]);
            __half2 h3 = __floats2half2_rn(s[mt][2*kv+1][2], s[mt][2*kv+1][3]);
            pa[mt][kv][0] = *reinterpret_cast<uint32_t*>(&h0);
            pa[mt][kv][1] = *reinterpret_cast<uint32_t*>(&h1);
            pa[mt][kv][2] = *reinterpret_cast<uint32_t*>(&h2);
            pa[mt][kv][3] = *reinterpret_cast<uint32_t*>(&h3);
          }

        // ---- O += P Vh (V fragments reused across 2 m-subtiles) -------------
        #pragma unroll
        for (int kv = 0; kv < 4; kv++) {
            #pragma unroll
            for (int np = 0; np < 4; np++) {
                const uint32_t vo = (uint32_t)(((np*16 + b_ro)*TST + kv*16 + b_co)*2);
                uint32_t v0h, v1h, v2h, v3h;
                LDSM4(v0h, v1h, v2h, v3h, base + vhst + vo);
                uint32_t vhA[2] = {v0h, v1h}, vhB[2] = {v2h, v3h};
                #pragma unroll
                for (int mt = 0; mt < 2; mt++) {
                    mma_f16(o[mt][2*np  ], pa[mt][kv], vhA);
                    mma_f16(o[mt][2*np+1], pa[mt][kv], vhB);
                }
            }
        }
        __syncthreads();
    }

    // epilogue: normalize, split, store hi/lo planes for the O-GEMM
    #pragma unroll
    for (int mt = 0; mt < 2; mt++)
      #pragma unroll
      for (int hf = 0; hf < 2; hf++) {
        const int r = q0 + wr + mt*16 + g + hf*8;
        const float inv = 1.f / lrun[mt][hf];
        #pragma unroll
        for (int nt = 0; nt < 8; nt++) {
            const int col = h*DK_ + nt*8 + c*2;
            uint32_t h2, l2;
            split2(o[mt][nt][hf*2]*inv, o[mt][nt][hf*2+1]*inv, h2, l2);
            const size_t off = (((size_t)b*S_ + r)*D_ + col) >> 1;
            ((uint32_t*)g_aph)[off] = h2;
            ((uint32_t*)g_apl)[off] = l2;
        }
      }
}

// ---------------- launch ------------------------------------------------------
extern "C" void kernel_launch(void* const* d_in, const int* in_sizes, int n_in,
                              void* d_out, int out_size)
{
    (void)in_sizes; (void)n_in; (void)out_size;
    const float* Q  = (const float*)d_in[0];
    const float* K  = (const float*)d_in[1];
    const float* V  = (const float*)d_in[2];
    const float* Wq = (const float*)d_in[3];
    const float* bq = (const float*)d_in[4];
    const float* Wk = (const float*)d_in[5];
    const float* bk = (const float*)d_in[6];
    const float* Wv = (const float*)d_in[7];
    const float* bv = (const float*)d_in[8];
    const float* Wo = (const float*)d_in[9];
    const float* bo = (const float*)d_in[10];
    float* out = (float*)d_out;

    cudaFuncSetAttribute(gemm_qkv, cudaFuncAttributeMaxDynamicSharedMemorySize, GEMM_SMEM);
    cudaFuncSetAttribute(gemm_out, cudaFuncAttributeMaxDynamicSharedMemorySize, GEMM_SMEM);
    cudaFuncSetAttribute(attn_f16, cudaFuncAttributeMaxDynamicSharedMemorySize, ATTN_SMEM);

    split_all<<<dim3(4096, 7), 256>>>((const float4*)Q,  (const float4*)K,
                                      (const float4*)V,  (const float4*)Wq,
                                      (const float4*)Wk, (const float4*)Wv,
                                      (const float4*)Wo);

    gemm_qkv<<<dim3(M_/128, D_/128, 3), 128, GEMM_SMEM>>>(bq, bk, bv);

    attn_f16<<<dim3(S_/128, H_, B_), 128, ATTN_SMEM>>>();

    gemm_out<<<dim3(M_/128, D_/128), 128, GEMM_SMEM>>>(bo, out);
}

// round 17
// speedup vs baseline: 1.2859x; 1.1543x over previous
#include <cuda_runtime.h>
#include <cuda_fp16.h>
#include <math.h>
#include <stdint.h>

#define B_  2
#define S_  2048
#define D_  1024
#define H_  16
#define DK_ 64
#define M_  (B_*S_)   // 4096

// ---------------- scratch ------------------------------------------------------
__device__ __half g_qih[(size_t)M_*D_]; __device__ __half g_qil[(size_t)M_*D_];
__device__ __half g_kih[(size_t)M_*D_];
__device__ __half g_vih[(size_t)M_*D_];
__device__ __half g_wqh[(size_t)D_*D_];
__device__ __half g_wkh[(size_t)D_*D_];
__device__ __half g_wvh[(size_t)D_*D_];
__device__ __half g_woh[(size_t)D_*D_];
__device__ __half g_qph[(size_t)B_*H_*S_*DK_]; __device__ __half g_qpl[(size_t)B_*H_*S_*DK_];
__device__ __half g_kph[(size_t)B_*H_*S_*DK_];
__device__ __half g_vth[(size_t)B_*H_*DK_*S_];
__device__ __half g_aph[(size_t)M_*D_]; __device__ __half g_apl[(size_t)M_*D_];

// ---------------- helpers -----------------------------------------------------
__device__ __forceinline__ uint32_t smem_to_u32(const void* p) {
    uint32_t a;
    asm("{ .reg .u64 t; cvta.to.shared.u64 t, %1; cvt.u32.u64 %0, t; }"
        : "=r"(a) : "l"(p));
    return a;
}
__device__ __forceinline__ void cp_async16(uint32_t dst, const void* src) {
    asm volatile("cp.async.ca.shared.global [%0], [%1], 16;" :: "r"(dst), "l"(src));
}
#define CP_COMMIT() asm volatile("cp.async.commit_group;" ::: "memory")
#define CP_WAIT(n)  asm volatile("cp.async.wait_group %0;" :: "n"(n) : "memory")

#define LDSM4(r0,r1,r2,r3,addr) \
    asm volatile("ldmatrix.sync.aligned.m8n8.x4.shared.b16 {%0,%1,%2,%3}, [%4];" \
        : "=r"(r0),"=r"(r1),"=r"(r2),"=r"(r3) : "r"(addr))

__device__ __forceinline__ void split2(float x, float y, uint32_t& h2, uint32_t& l2) {
    __half2 hp = __floats2half2_rn(x, y);
    const float lx = x - __half2float(__low2half(hp));
    const float ly = y - __half2float(__high2half(hp));
    __half2 lp = __floats2half2_rn(lx, ly);
    h2 = *reinterpret_cast<uint32_t*>(&hp);
    l2 = *reinterpret_cast<uint32_t*>(&lp);
}

__device__ __forceinline__ void mma_f16(float* d, const uint32_t* a, const uint32_t* b) {
    asm("mma.sync.aligned.m16n8k16.row.col.f32.f16.f16.f32 "
        "{%0,%1,%2,%3}, {%4,%5,%6,%7}, {%8,%9}, {%0,%1,%2,%3};"
        : "+f"(d[0]), "+f"(d[1]), "+f"(d[2]), "+f"(d[3])
        : "r"(a[0]), "r"(a[1]), "r"(a[2]), "r"(a[3]), "r"(b[0]), "r"(b[1]));
}

// ---------------- prep: Q hi+lo, K/V/weights hi-only, one launch --------------
__global__ __launch_bounds__(256) void split_all(
    const float4* __restrict__ q,  const float4* __restrict__ k,
    const float4* __restrict__ v,  const float4* __restrict__ wq,
    const float4* __restrict__ wk, const float4* __restrict__ wv,
    const float4* __restrict__ wo)
{
    const int t = blockIdx.y;
    const size_t i = (size_t)blockIdx.x * 256 + threadIdx.x;   // per float4
    const size_t n = (t < 3) ? (size_t)M_*D_/4 : (size_t)D_*D_/4;
    if (i >= n) return;
    const float4* src; __half *dh, *dl = nullptr;
    switch (t) {
        case 0:  src = q;  dh = g_qih; dl = g_qil; break;
        case 1:  src = k;  dh = g_kih; break;
        case 2:  src = v;  dh = g_vih; break;
        case 3:  src = wq; dh = g_wqh; break;
        case 4:  src = wk; dh = g_wkh; break;
        case 5:  src = wv; dh = g_wvh; break;
        default: src = wo; dh = g_woh; break;
    }
    const float4 x = src[i];
    uint32_t h0, l0, h1, l1;
    split2(x.x, x.y, h0, l0);
    split2(x.z, x.w, h1, l1);
    ((uint2*)dh)[i] = make_uint2(h0, h1);
    if (dl) ((uint2*)dl)[i] = make_uint2(l0, l1);
}

// ---------------- GEMM mainloop: 4 warps, warp-tile 64x64, TERMS 1 or 2 -------
#define AST 40                          // halves per smem row (32 + 8 pad)
#define PLANE (128*AST)                 // halves per stage-plane
#define GEMM_SMEM 69632                 // max(3 planes x 2 stages = 61440, V-tile 67584)

template<int TERMS>
__device__ __forceinline__ void gemm_mainloop(
    const __half* __restrict__ Agh, const __half* __restrict__ Agl,
    const __half* __restrict__ Wgh,
    uint32_t sAh, uint32_t sAl, uint32_t sBh,
    int m0, int n0, int tid, int wm, int wn, int lane,
    float acc[4][8][4])
{
    const int lr = lane & 7;
    const int a_ro = lr + ((lane >> 3) & 1) * 8;   // A ldmatrix row offset
    const int a_co = ((lane >> 4) & 1) * 8;        // A col offset
    const int b_ro = lr + ((lane >> 4) & 1) * 8;   // B row offset
    const int b_co = ((lane >> 3) & 1) * 8;        // B col offset

    #define G_LOAD(st, chk) do { \
        _Pragma("unroll") \
        for (int i = 0; i < 4; i++) { \
            const int idx = tid + i*128, row = idx >> 2, seg = idx & 3; \
            const uint32_t so = (uint32_t)((((st)*128+row)*AST + seg*8)*2); \
            cp_async16(sAh + so, Agh + (size_t)(m0+row)*1024 + (chk)*32 + seg*8); \
            if (TERMS == 2) \
                cp_async16(sAl + so, Agl + (size_t)(m0+row)*1024 + (chk)*32 + seg*8); \
            cp_async16(sBh + so, Wgh + (size_t)(n0+row)*1024 + (chk)*32 + seg*8); \
        } \
    } while (0)

    G_LOAD(0, 0); CP_COMMIT();

    for (int chk = 0; chk < 32; chk++) {
        const int st = chk & 1;
        if (chk < 31) { G_LOAD(st^1, chk+1); CP_COMMIT(); CP_WAIT(1); }
        else CP_WAIT(0);
        __syncthreads();

        const uint32_t stoff = (uint32_t)(st*PLANE*2);
        #pragma unroll
        for (int ks = 0; ks < 2; ks++) {
            uint32_t ah[4][4], al[4][4];
            #pragma unroll
            for (int mt = 0; mt < 4; mt++) {
                const uint32_t ao = stoff +
                    (uint32_t)(((wm + mt*16 + a_ro)*AST + ks*16 + a_co)*2);
                LDSM4(ah[mt][0], ah[mt][1], ah[mt][2], ah[mt][3], sAh + ao);
                if (TERMS == 2)
                    LDSM4(al[mt][0], al[mt][1], al[mt][2], al[mt][3], sAl + ao);
            }
            #pragma unroll
            for (int np = 0; np < 4; np++) {
                const uint32_t bo = stoff +
                    (uint32_t)(((wn + np*16 + b_ro)*AST + ks*16 + b_co)*2);
                uint32_t b0h, b1h, b2h, b3h;
                LDSM4(b0h, b1h, b2h, b3h, sBh + bo);
                uint32_t bhA[2] = {b0h, b1h}, bhB[2] = {b2h, b3h};
                #pragma unroll
                for (int mt = 0; mt < 4; mt++) {
                    mma_f16(acc[mt][2*np  ], ah[mt], bhA);
                    mma_f16(acc[mt][2*np+1], ah[mt], bhB);
                }
                if (TERMS == 2) {
                    #pragma unroll
                    for (int mt = 0; mt < 4; mt++) {
                        mma_f16(acc[mt][2*np  ], al[mt], bhA);
                        mma_f16(acc[mt][2*np+1], al[mt], bhB);
                    }
                }
            }
        }
        __syncthreads();
    }
    #undef G_LOAD
}

// ---------------- merged Q/K/V projection GEMM (128 threads) ------------------
// z=0: Q 2-term -> hi+lo planes. z=1: K 1-term -> hi. z=2: V 1-term -> V^T hi.
__global__ __launch_bounds__(128, 2) void gemm_qkv(
    const float* __restrict__ bq, const float* __restrict__ bk,
    const float* __restrict__ bv)
{
    extern __shared__ __half smh[];
    const uint32_t base = smem_to_u32(smh);
    const uint32_t sAh = base, sAl = base + 2*PLANE*2, sBh = base + 4*PLANE*2;
    const int tid = threadIdx.x, lane = tid & 31, wid = tid >> 5;
    const int g = lane >> 2, c = lane & 3;
    const int wm = (wid & 1)*64, wn = (wid >> 1)*64;
    const int m0 = blockIdx.x*128, n0 = blockIdx.y*128;
    const int z = blockIdx.z;

    float acc[4][8][4] = {};
    if (z == 0)
        gemm_mainloop<2>(g_qih, g_qil, g_wqh, sAh, sAl, sBh, m0, n0, tid, wm, wn, lane, acc);
    else if (z == 1)
        gemm_mainloop<1>(g_kih, nullptr, g_wkh, sAh, sAl, sBh, m0, n0, tid, wm, wn, lane, acc);
    else
        gemm_mainloop<1>(g_vih, nullptr, g_wvh, sAh, sAl, sBh, m0, n0, tid, wm, wn, lane, acc);

    if (z == 0) {
        #pragma unroll
        for (int mt = 0; mt < 4; mt++)
          #pragma unroll
          for (int hf = 0; hf < 2; hf++) {
            const int m = m0 + wm + mt*16 + g + hf*8;
            const int bb = m >> 11, ss = m & (S_-1);
            #pragma unroll
            for (int nt = 0; nt < 8; nt++) {
                const int n = n0 + wn + nt*8 + c*2;
                const int hh = n >> 6, dk = n & 63;
                uint32_t h2, l2;
                split2(acc[mt][nt][hf*2+0] + bq[n],
                       acc[mt][nt][hf*2+1] + bq[n+1], h2, l2);
                const size_t o = ((((size_t)bb*H_ + hh)*S_ + ss)*DK_ + dk) >> 1;
                ((uint32_t*)g_qph)[o] = h2;
                ((uint32_t*)g_qpl)[o] = l2;
            }
          }
    } else if (z == 1) {
        #pragma unroll
        for (int mt = 0; mt < 4; mt++)
          #pragma unroll
          for (int hf = 0; hf < 2; hf++) {
            const int m = m0 + wm + mt*16 + g + hf*8;
            const int bb = m >> 11, ss = m & (S_-1);
            #pragma unroll
            for (int nt = 0; nt < 8; nt++) {
                const int n = n0 + wn + nt*8 + c*2;
                const int hh = n >> 6, dk = n & 63;
                const __half2 hp = __floats2half2_rn(acc[mt][nt][hf*2+0] + bk[n],
                                                     acc[mt][nt][hf*2+1] + bk[n+1]);
                const size_t o = ((((size_t)bb*H_ + hh)*S_ + ss)*DK_ + dk) >> 1;
                ((__half2*)g_kph)[o] = hp;
            }
          }
    } else {
        float* tile = (float*)smh;   // [128 n][132]
        __syncthreads();
        #pragma unroll
        for (int mt = 0; mt < 4; mt++)
          #pragma unroll
          for (int hf = 0; hf < 2; hf++) {
            const int ml = wm + mt*16 + g + hf*8;
            #pragma unroll
            for (int nt = 0; nt < 8; nt++) {
                const int nl = wn + nt*8 + c*2;
                tile[(nl  )*132 + ml] = acc[mt][nt][hf*2+0] + bv[n0+nl];
                tile[(nl+1)*132 + ml] = acc[mt][nt][hf*2+1] + bv[n0+nl+1];
            }
          }
        __syncthreads();
        const int bb = m0 >> 11, s0 = m0 & (S_-1);
        #pragma unroll
        for (int i = 0; i < 64; i++) {
            const int idx = tid + i*128;      // 0..8191
            const int nl = idx >> 6;          // 0..127
            const int sp = idx & 63;          // 0..63 (s-pair)
            const int hh = (n0 + nl) >> 6, dk = (n0 + nl) & 63;
            const __half2 hp = __floats2half2_rn(tile[nl*132 + 2*sp],
                                                 tile[nl*132 + 2*sp + 1]);
            const size_t o = ((((size_t)bb*H_ + hh)*DK_ + dk)*S_ + s0 + 2*sp) >> 1;
            ((__half2*)g_vth)[o] = hp;
        }
    }
}

// ---------------- output GEMM (128 threads, 2-term) ---------------------------
__global__ __launch_bounds__(128, 2) void gemm_out(const float* __restrict__ bias,
                                                   float* __restrict__ C)
{
    extern __shared__ __half smh[];
    const uint32_t base = smem_to_u32(smh);
    const uint32_t sAh = base, sAl = base + 2*PLANE*2, sBh = base + 4*PLANE*2;
    const int tid = threadIdx.x, lane = tid & 31, wid = tid >> 5;
    const int g = lane >> 2, c = lane & 3;
    const int wm = (wid & 1)*64, wn = (wid >> 1)*64;
    const int m0 = blockIdx.x*128, n0 = blockIdx.y*128;

    float acc[4][8][4] = {};
    gemm_mainloop<2>(g_aph, g_apl, g_woh, sAh, sAl, sBh, m0, n0, tid, wm, wn, lane, acc);

    #pragma unroll
    for (int mt = 0; mt < 4; mt++)
      #pragma unroll
      for (int hf = 0; hf < 2; hf++) {
        const int m = m0 + wm + mt*16 + g + hf*8;
        #pragma unroll
        for (int nt = 0; nt < 8; nt++) {
            const int n = n0 + wn + nt*8 + c*2;
            *(float2*)(C + (size_t)m*D_ + n) =
                make_float2(acc[mt][nt][hf*2+0] + bias[n],
                            acc[mt][nt][hf*2+1] + bias[n+1]);
        }
      }
}

// ---------------- fp16 flash attention: 4 warps x 32 q-rows, Q in regs --------
#define TST 72                          // halves per smem row (64 + 8 pad)
#define SM_QH 0
#define SM_QL (128*TST)
#define SM_KH (2*128*TST)
#define SM_VH (SM_KH + 2*64*TST)
#define ATTN_SMEM ((SM_VH + 2*64*TST)*2)   // 73728 B

__global__ __launch_bounds__(128, 2) void attn_f16()
{
    extern __shared__ __half smh[];
    const uint32_t base = smem_to_u32(smh);
    const int tid = threadIdx.x, lane = tid & 31, wid = tid >> 5;
    const int g = lane >> 2, c = lane & 3;
    const int wr = wid * 32;                 // 4 warps x 32 q-rows
    const int h = blockIdx.y, b = blockIdx.z;
    const int q0 = blockIdx.x * 128;
    const size_t bh = (size_t)b*H_ + h;
    const __half* qgh = g_qph + (bh*S_ + q0)*DK_;
    const __half* qgl = g_qpl + (bh*S_ + q0)*DK_;
    const __half* kgh = g_kph + bh*S_*DK_;
    const __half* vgh = g_vth + bh*DK_*S_;

    const int lr = lane & 7;
    const int a_ro = lr + ((lane >> 3) & 1) * 8;
    const int a_co = ((lane >> 4) & 1) * 8;
    const int b_ro = lr + ((lane >> 4) & 1) * 8;
    const int b_co = ((lane >> 3) & 1) * 8;

    // prologue: Q planes + K/V tile 0
    #pragma unroll
    for (int i = 0; i < 8; i++) {
        const int idx = tid + i*128;          // 0..1023
        const int row = idx >> 3, seg = idx & 7;
        const uint32_t so = (uint32_t)((row*TST + seg*8)*2);
        cp_async16(base + SM_QH*2 + so, qgh + (size_t)row*DK_ + seg*8);
        cp_async16(base + SM_QL*2 + so, qgl + (size_t)row*DK_ + seg*8);
    }
    #pragma unroll
    for (int i = 0; i < 4; i++) {
        const int idx = tid + i*128;          // 0..511
        const int row = idx >> 3, seg = idx & 7;
        const uint32_t so = (uint32_t)((row*TST + seg*8)*2);
        cp_async16(base + SM_KH*2 + so, kgh + (size_t)row*DK_ + seg*8);
        cp_async16(base + SM_VH*2 + so, vgh + (size_t)row*S_ + seg*8);
    }
    CP_COMMIT();

    // Q fragments cached in registers for the whole mainloop (loaded at t=0)
    uint32_t qfh[2][4][4], qfl[2][4][4];

    float o[2][8][4] = {};
    float mrun[2][2] = {{-1e30f,-1e30f},{-1e30f,-1e30f}};
    float lrun[2][2] = {{0.f,0.f},{0.f,0.f}};

    for (int t = 0; t < S_/64; t++) {
        const int st = t & 1;
        if (t < S_/64 - 1) {
            const int s2 = st ^ 1;
            #pragma unroll
            for (int i = 0; i < 4; i++) {
                const int idx = tid + i*128;
                const int row = idx >> 3, seg = idx & 7;
                const uint32_t so = (uint32_t)(((s2*64 + row)*TST + seg*8)*2);
                cp_async16(base + SM_KH*2 + so, kgh + (size_t)((t+1)*64+row)*DK_ + seg*8);
                cp_async16(base + SM_VH*2 + so, vgh + (size_t)row*S_ + (t+1)*64 + seg*8);
            }
            CP_COMMIT(); CP_WAIT(1);
        } else {
            CP_WAIT(0);
        }
        __syncthreads();

        if (t == 0) {
            #pragma unroll
            for (int mt = 0; mt < 2; mt++)
                #pragma unroll
                for (int ks = 0; ks < 4; ks++) {
                    const uint32_t qo =
                        (uint32_t)(((wr + mt*16 + a_ro)*TST + ks*16 + a_co)*2);
                    LDSM4(qfh[mt][ks][0], qfh[mt][ks][1], qfh[mt][ks][2], qfh[mt][ks][3],
                          base + SM_QH*2 + qo);
                    LDSM4(qfl[mt][ks][0], qfl[mt][ks][1], qfl[mt][ks][2], qfl[mt][ks][3],
                          base + SM_QL*2 + qo);
                }
        }

        const uint32_t kst  = (uint32_t)((SM_KH + st*64*TST)*2);
        const uint32_t vhst = (uint32_t)((SM_VH + st*64*TST)*2);

        // ---- S = (Q K^T)/8  = (Qh+Ql)·Kh, Q from registers ------------------
        float s[2][8][4] = {};
        #pragma unroll
        for (int ks = 0; ks < 4; ks++) {
            #pragma unroll
            for (int np = 0; np < 4; np++) {
                const uint32_t ko = (uint32_t)(((np*16 + b_ro)*TST + ks*16 + b_co)*2);
                uint32_t b0h, b1h, b2h, b3h;
                LDSM4(b0h, b1h, b2h, b3h, base + kst + ko);
                uint32_t bhA[2] = {b0h, b1h}, bhB[2] = {b2h, b3h};
                #pragma unroll
                for (int mt = 0; mt < 2; mt++) {
                    mma_f16(s[mt][2*np  ], qfh[mt][ks], bhA);
                    mma_f16(s[mt][2*np+1], qfh[mt][ks], bhB);
                }
                #pragma unroll
                for (int mt = 0; mt < 2; mt++) {
                    mma_f16(s[mt][2*np  ], qfl[mt][ks], bhA);
                    mma_f16(s[mt][2*np+1], qfl[mt][ks], bhB);
                }
            }
        }

        // ---- online softmax (per mt: rows g, g+8; stats across 4 c-lanes) ---
        #pragma unroll
        for (int mt = 0; mt < 2; mt++)
          #pragma unroll
          for (int hf = 0; hf < 2; hf++) {
            float mx = -1e30f;
            #pragma unroll
            for (int nt = 0; nt < 8; nt++) {
                s[mt][nt][hf*2]   *= 0.125f;
                s[mt][nt][hf*2+1] *= 0.125f;
                mx = fmaxf(mx, fmaxf(s[mt][nt][hf*2], s[mt][nt][hf*2+1]));
            }
            mx = fmaxf(mx, __shfl_xor_sync(0xffffffffu, mx, 1));
            mx = fmaxf(mx, __shfl_xor_sync(0xffffffffu, mx, 2));
            const float mn = fmaxf(mrun[mt][hf], mx);
            const float corr = __expf(mrun[mt][hf] - mn);
            mrun[mt][hf] = mn;
            float ls = 0.f;
            #pragma unroll
            for (int nt = 0; nt < 8; nt++) {
                const float e0 = __expf(s[mt][nt][hf*2]   - mn);
                const float e1 = __expf(s[mt][nt][hf*2+1] - mn);
                s[mt][nt][hf*2] = e0; s[mt][nt][hf*2+1] = e1;
                ls += e0 + e1;
            }
            ls += __shfl_xor_sync(0xffffffffu, ls, 1);
            ls += __shfl_xor_sync(0xffffffffu, ls, 2);
            lrun[mt][hf] = lrun[mt][hf]*corr + ls;
            #pragma unroll
            for (int nt = 0; nt < 8; nt++) {
                o[mt][nt][hf*2]   *= corr;
                o[mt][nt][hf*2+1] *= corr;
            }
          }

        // ---- P fragments directly from acc registers ------------------------
        uint32_t pa[2][4][4];
        #pragma unroll
        for (int mt = 0; mt < 2; mt++)
          #pragma unroll
          for (int kv = 0; kv < 4; kv++) {
            __half2 h0 = __floats2half2_rn(s[mt][2*kv  ][0], s[mt][2*kv  ][1]);
            __half2 h1 = __floats2half2_rn(s[mt][2*kv  ][2], s[mt][2*kv  ][3]);
            __half2 h2 = __floats2half2_rn(s[mt][2*kv+1][0], s[mt][2*kv+1][1]);
            __half2 h3 = __floats2half2_rn(s[mt][2*kv+1][2], s[mt][2*kv+1][3]);
            pa[mt][kv][0] = *reinterpret_cast<uint32_t*>(&h0);
            pa[mt][kv][1] = *reinterpret_cast<uint32_t*>(&h1);
            pa[mt][kv][2] = *reinterpret_cast<uint32_t*>(&h2);
            pa[mt][kv][3] = *reinterpret_cast<uint32_t*>(&h3);
          }

        // ---- O += P Vh (V fragments reused across 2 m-subtiles) -------------
        #pragma unroll
        for (int kv = 0; kv < 4; kv++) {
            #pragma unroll
            for (int np = 0; np < 4; np++) {
                const uint32_t vo = (uint32_t)(((np*16 + b_ro)*TST + kv*16 + b_co)*2);
                uint32_t v0h, v1h, v2h, v3h;
                LDSM4(v0h, v1h, v2h, v3h, base + vhst + vo);
                uint32_t vhA[2] = {v0h, v1h}, vhB[2] = {v2h, v3h};
                #pragma unroll
                for (int mt = 0; mt < 2; mt++) {
                    mma_f16(o[mt][2*np  ], pa[mt][kv], vhA);
                    mma_f16(o[mt][2*np+1], pa[mt][kv], vhB);
                }
            }
        }
        __syncthreads();
    }

    // epilogue: normalize, split, store hi/lo planes for the O-GEMM
    #pragma unroll
    for (int mt = 0; mt < 2; mt++)
      #pragma unroll
      for (int hf = 0; hf < 2; hf++) {
        const int r = q0 + wr + mt*16 + g + hf*8;
        const float inv = 1.f / lrun[mt][hf];
        #pragma unroll
        for (int nt = 0; nt < 8; nt++) {
            const int col = h*DK_ + nt*8 + c*2;
            uint32_t h2, l2;
            split2(o[mt][nt][hf*2]*inv, o[mt][nt][hf*2+1]*inv, h2, l2);
            const size_t off = (((size_t)b*S_ + r)*D_ + col) >> 1;
            ((uint32_t*)g_aph)[off] = h2;
            ((uint32_t*)g_apl)[off] = l2;
        }
      }
}

// ---------------- launch ------------------------------------------------------
extern "C" void kernel_launch(void* const* d_in, const int* in_sizes, int n_in,
                              void* d_out, int out_size)
{
    (void)in_sizes; (void)n_in; (void)out_size;
    const float* Q  = (const float*)d_in[0];
    const float* K  = (const float*)d_in[1];
    const float* V  = (const float*)d_in[2];
    const float* Wq = (const float*)d_in[3];
    const float* bq = (const float*)d_in[4];
    const float* Wk = (const float*)d_in[5];
    const float* bk = (const float*)d_in[6];
    const float* Wv = (const float*)d_in[7];
    const float* bv = (const float*)d_in[8];
    const float* Wo = (const float*)d_in[9];
    const float* bo = (const float*)d_in[10];
    float* out = (float*)d_out;

    cudaFuncSetAttribute(gemm_qkv, cudaFuncAttributeMaxDynamicSharedMemorySize, GEMM_SMEM);
    cudaFuncSetAttribute(gemm_out, cudaFuncAttributeMaxDynamicSharedMemorySize, GEMM_SMEM);
    cudaFuncSetAttribute(attn_f16, cudaFuncAttributeMaxDynamicSharedMemorySize, ATTN_SMEM);

    split_all<<<dim3(4096, 7), 256>>>((const float4*)Q,  (const float4*)K,
                                      (const float4*)V,  (const float4*)Wq,
                                      (const float4*)Wk, (const float4*)Wv,
                                      (const float4*)Wo);

    gemm_qkv<<<dim3(M_/128, D_/128, 3), 128, GEMM_SMEM>>>(bq, bk, bv);

    attn_f16<<<dim3(S_/128, H_, B_), 128, ATTN_SMEM>>>();

    gemm_out<<<dim3(M_/128, D_/128), 128, GEMM_SMEM>>>(bo, out);
}